// round 1
// baseline (speedup 1.0000x reference)
#include <cuda_runtime.h>
#include <cstddef>

// Problem constants
#define BB 8
#define LL 2048
#define DD 256

// Scratch (allocation-free rule: __device__ globals)
__device__ float g_K[(size_t)BB * LL * DD];          // 16.8 MB
__device__ float g_V[(size_t)BB * LL * DD];          // 16.8 MB
__device__ float g_E[(size_t)BB * LL * LL];          // 134 MB

// ---------------------------------------------------------------------------
// Generic batched SGEMM:  C[m,n] = alpha * sum_k A[m,k] * B(k,n)  (+ bias[n])
//   A is row-major [M,K] (lda == K), batch stride sA
//   BNT=true : B is [N,K] K-major (ldb = K)   -> C = A * B^T   (NT)
//   BNT=false: B is [K,N] N-major (ldb = N)   -> C = A * B     (NN)
//   C row-major with leading dim ldc, batch stride sC
// Tiles: BM=128, BN=64, BK=16, 256 threads, 8x4 per thread.
// All problem dims here divide the tiles exactly -> no bounds checks.
// ---------------------------------------------------------------------------
#define BM 128
#define BN 64
#define BK 16
#define TM 8
#define TN 4

template <bool BNT>
__global__ __launch_bounds__(256)
void gemm_kernel(const float* __restrict__ A, size_t sA,
                 const float* __restrict__ Bm, size_t sB, int ldb,
                 float* __restrict__ C, size_t sC, int ldc,
                 int K, float alpha, const float* __restrict__ bias)
{
    __shared__ float As[BK][BM];
    __shared__ float Bs[BK][BN];

    const int bz = blockIdx.z;
    A  += (size_t)bz * sA;
    Bm += (size_t)bz * sB;
    C  += (size_t)bz * sC;

    const int n0 = blockIdx.x * BN;
    const int m0 = blockIdx.y * BM;

    const int tid = threadIdx.x;
    const int tx = tid & 15;   // n direction (16 * TN = 64)
    const int ty = tid >> 4;   // m direction (16 * TM = 128)

    float acc[TM][TN];
#pragma unroll
    for (int i = 0; i < TM; i++)
#pragma unroll
        for (int j = 0; j < TN; j++) acc[i][j] = 0.0f;

    for (int k0 = 0; k0 < K; k0 += BK) {
        // --- load A tile (128 rows x 16 k) = 512 float4, 2 per thread,
        //     stored transposed As[k][m]
#pragma unroll
        for (int l = 0; l < 2; l++) {
            int f   = tid + l * 256;
            int row = f >> 2;          // 0..127
            int kq  = (f & 3) * 4;     // 0,4,8,12
            float4 v = *reinterpret_cast<const float4*>(
                &A[(size_t)(m0 + row) * K + k0 + kq]);
            As[kq + 0][row] = v.x;
            As[kq + 1][row] = v.y;
            As[kq + 2][row] = v.z;
            As[kq + 3][row] = v.w;
        }
        // --- load B tile
        if constexpr (BNT) {
            // B[n, k] K-major: 64 n x 16 k = 256 float4, 1 per thread
            int n  = tid >> 2;         // 0..63
            int kq = (tid & 3) * 4;
            float4 v = *reinterpret_cast<const float4*>(
                &Bm[(size_t)(n0 + n) * ldb + k0 + kq]);
            Bs[kq + 0][n] = v.x;
            Bs[kq + 1][n] = v.y;
            Bs[kq + 2][n] = v.z;
            Bs[kq + 3][n] = v.w;
        } else {
            // B[k, n] N-major: 16 k x 64 n = 256 float4, 1 per thread
            int kk = tid >> 4;         // 0..15
            int nq = (tid & 15) * 4;
            float4 v = *reinterpret_cast<const float4*>(
                &Bm[(size_t)(k0 + kk) * ldb + n0 + nq]);
            *reinterpret_cast<float4*>(&Bs[kk][nq]) = v;
        }
        __syncthreads();

#pragma unroll
        for (int kk = 0; kk < BK; kk++) {
            float a[TM], bv[TN];
            float4 a0 = *reinterpret_cast<const float4*>(&As[kk][ty * TM]);
            float4 a1 = *reinterpret_cast<const float4*>(&As[kk][ty * TM + 4]);
            a[0] = a0.x; a[1] = a0.y; a[2] = a0.z; a[3] = a0.w;
            a[4] = a1.x; a[5] = a1.y; a[6] = a1.z; a[7] = a1.w;
            float4 b0 = *reinterpret_cast<const float4*>(&Bs[kk][tx * TN]);
            bv[0] = b0.x; bv[1] = b0.y; bv[2] = b0.z; bv[3] = b0.w;
#pragma unroll
            for (int i = 0; i < TM; i++)
#pragma unroll
                for (int j = 0; j < TN; j++)
                    acc[i][j] = fmaf(a[i], bv[j], acc[i][j]);
        }
        __syncthreads();
    }

    // --- epilogue
    float bv[TN] = {0.f, 0.f, 0.f, 0.f};
    if (bias != nullptr) {
        float4 bb = *reinterpret_cast<const float4*>(&bias[n0 + tx * TN]);
        bv[0] = bb.x; bv[1] = bb.y; bv[2] = bb.z; bv[3] = bb.w;
    }
#pragma unroll
    for (int i = 0; i < TM; i++) {
        float4 o;
        o.x = fmaf(acc[i][0], alpha, bv[0]);
        o.y = fmaf(acc[i][1], alpha, bv[1]);
        o.z = fmaf(acc[i][2], alpha, bv[2]);
        o.w = fmaf(acc[i][3], alpha, bv[3]);
        *reinterpret_cast<float4*>(
            &C[(size_t)(m0 + ty * TM + i) * ldc + n0 + tx * TN]) = o;
    }
}

// ---------------------------------------------------------------------------
// Column softmax: A[b, :, k] = softmax over q of E[b, :, k].
// One thread owns one column k; loads are coalesced across threads.
// 3 passes over E (max / sum / normalized write), exp recomputed (cheap MUFU)
// to avoid an extra A read-modify-write pass.
// ---------------------------------------------------------------------------
__global__ __launch_bounds__(64)
void softmax_col_kernel(const float* __restrict__ E, float* __restrict__ Aout)
{
    const int b = blockIdx.y;
    const int k = blockIdx.x * 64 + threadIdx.x;
    const float* Eb = E + (size_t)b * LL * LL + k;
    float* Ab = Aout + (size_t)b * LL * LL + k;

    float m = -1e30f;
#pragma unroll 8
    for (int q = 0; q < LL; q++)
        m = fmaxf(m, Eb[(size_t)q * LL]);

    float s = 0.0f;
#pragma unroll 8
    for (int q = 0; q < LL; q++)
        s += __expf(Eb[(size_t)q * LL] - m);

    const float inv = 1.0f / s;
#pragma unroll 8
    for (int q = 0; q < LL; q++)
        Ab[(size_t)q * LL] = __expf(Eb[(size_t)q * LL] - m) * inv;
}

// ---------------------------------------------------------------------------
// Launch
// ---------------------------------------------------------------------------
extern "C" void kernel_launch(void* const* d_in, const int* in_sizes, int n_in,
                              void* d_out, int out_size)
{
    const float* x  = (const float*)d_in[0];
    const float* Wq = (const float*)d_in[1];
    const float* bq = (const float*)d_in[2];
    const float* Wk = (const float*)d_in[3];
    const float* bk = (const float*)d_in[4];
    const float* Wv = (const float*)d_in[5];
    const float* bv = (const float*)d_in[6];

    float* out  = (float*)d_out;
    float* Sp   = out;                                  // [B, 2L, D]
    float* Aout = out + (size_t)BB * 2 * LL * DD;       // [B, L, L]

    float *gK, *gV, *gE;
    cudaGetSymbolAddress((void**)&gK, g_K);
    cudaGetSymbolAddress((void**)&gV, g_V);
    cudaGetSymbolAddress((void**)&gE, g_E);

    const size_t sX  = (size_t)LL * DD;       // x batch stride
    const size_t sSp = (size_t)2 * LL * DD;   // S_p batch stride
    const size_t sE  = (size_t)LL * LL;

    dim3 gProj(DD / BN, LL / BM, BB);   // (4, 16, 8)
    dim3 gE_(LL / BN, LL / BM, BB);     // (32, 16, 8)

    // Q -> d_out S_p first half (per-batch rows are contiguous there)
    gemm_kernel<true><<<gProj, 256>>>(x, sX, Wq, 0, DD, Sp, sSp, DD,
                                      DD, 1.0f, bq);
    // K, V -> scratch
    gemm_kernel<true><<<gProj, 256>>>(x, sX, Wk, 0, DD, gK, sX, DD,
                                      DD, 1.0f, bk);
    gemm_kernel<true><<<gProj, 256>>>(x, sX, Wv, 0, DD, gV, sX, DD,
                                      DD, 1.0f, bv);
    // E = Q K^T / sqrt(256)
    gemm_kernel<true><<<gE_, 256>>>(Sp, sSp, gK, sX, DD, gE, sE, LL,
                                    DD, 1.0f / 16.0f, nullptr);
    // A = softmax over q (columns of E)
    softmax_col_kernel<<<dim3(LL / 64, BB), 64>>>(gE, Aout);
    // C = A V  -> S_p second half
    gemm_kernel<false><<<gProj, 256>>>(Aout, sE, gV, sX, DD,
                                       Sp + (size_t)LL * DD, sSp, DD,
                                       LL, 1.0f, nullptr);
    (void)in_sizes; (void)n_in; (void)out_size;
}

// round 2
// speedup vs baseline: 1.2875x; 1.2875x over previous
#include <cuda_runtime.h>
#include <cstddef>

// Problem constants
#define BB 8
#define LL 2048
#define DD 256

// Scratch (allocation-free rule: __device__ globals)
__device__ float g_K[(size_t)BB * LL * DD];          // 16.8 MB
__device__ float g_V[(size_t)BB * LL * DD];          // 16.8 MB
__device__ float g_E[(size_t)BB * LL * LL];          // 134 MB
__device__ float g_pm[BB][16][LL];                   // partial col max
__device__ float g_ps[BB][16][LL];                   // partial col sum
__device__ float g_m[BB][LL];                        // final col max
__device__ float g_is[BB][LL];                       // final 1/sum

// ---------------------------------------------------------------------------
// SGEMM body (at the 3-reg FFMA ceiling already; kept as-is from R1):
//   C[m,n] = alpha * sum_k A[m,k] * B(k,n)  (+ bias[n])
//   BNT=true : B is [N,K] K-major -> C = A * B^T
//   BNT=false: B is [K,N] N-major -> C = A * B
// Tiles: BM=128, BN=64, BK=16, 256 threads, 8x4 per thread. lda == K assumed.
// ---------------------------------------------------------------------------
#define BM 128
#define BN 64
#define BK 16
#define TM 8
#define TN 4

template <bool BNT>
__device__ __forceinline__ void gemm_body(
    const float* __restrict__ A, const float* __restrict__ Bm,
    float* __restrict__ C, int ldb, int ldc,
    int K, float alpha, const float* __restrict__ bias,
    int m0, int n0)
{
    __shared__ float As[BK][BM];
    __shared__ float Bs[BK][BN];

    const int tid = threadIdx.x;
    const int tx = tid & 15;   // n direction (16 * TN = 64)
    const int ty = tid >> 4;   // m direction (16 * TM = 128)

    float acc[TM][TN];
#pragma unroll
    for (int i = 0; i < TM; i++)
#pragma unroll
        for (int j = 0; j < TN; j++) acc[i][j] = 0.0f;

    for (int k0 = 0; k0 < K; k0 += BK) {
        // --- A tile (128 rows x 16 k) = 512 float4, 2 per thread, transposed
#pragma unroll
        for (int l = 0; l < 2; l++) {
            int f   = tid + l * 256;
            int row = f >> 2;
            int kq  = (f & 3) * 4;
            float4 v = *reinterpret_cast<const float4*>(
                &A[(size_t)(m0 + row) * K + k0 + kq]);
            As[kq + 0][row] = v.x;
            As[kq + 1][row] = v.y;
            As[kq + 2][row] = v.z;
            As[kq + 3][row] = v.w;
        }
        // --- B tile
        if constexpr (BNT) {
            int n  = tid >> 2;
            int kq = (tid & 3) * 4;
            float4 v = *reinterpret_cast<const float4*>(
                &Bm[(size_t)(n0 + n) * ldb + k0 + kq]);
            Bs[kq + 0][n] = v.x;
            Bs[kq + 1][n] = v.y;
            Bs[kq + 2][n] = v.z;
            Bs[kq + 3][n] = v.w;
        } else {
            int kk = tid >> 4;
            int nq = (tid & 15) * 4;
            float4 v = *reinterpret_cast<const float4*>(
                &Bm[(size_t)(k0 + kk) * ldb + n0 + nq]);
            *reinterpret_cast<float4*>(&Bs[kk][nq]) = v;
        }
        __syncthreads();

#pragma unroll
        for (int kk = 0; kk < BK; kk++) {
            float a[TM], bv[TN];
            float4 a0 = *reinterpret_cast<const float4*>(&As[kk][ty * TM]);
            float4 a1 = *reinterpret_cast<const float4*>(&As[kk][ty * TM + 4]);
            a[0] = a0.x; a[1] = a0.y; a[2] = a0.z; a[3] = a0.w;
            a[4] = a1.x; a[5] = a1.y; a[6] = a1.z; a[7] = a1.w;
            float4 b0 = *reinterpret_cast<const float4*>(&Bs[kk][tx * TN]);
            bv[0] = b0.x; bv[1] = b0.y; bv[2] = b0.z; bv[3] = b0.w;
#pragma unroll
            for (int i = 0; i < TM; i++)
#pragma unroll
                for (int j = 0; j < TN; j++)
                    acc[i][j] = fmaf(a[i], bv[j], acc[i][j]);
        }
        __syncthreads();
    }

    float bv[TN] = {0.f, 0.f, 0.f, 0.f};
    if (bias != nullptr) {
        float4 bb = *reinterpret_cast<const float4*>(&bias[n0 + tx * TN]);
        bv[0] = bb.x; bv[1] = bb.y; bv[2] = bb.z; bv[3] = bb.w;
    }
#pragma unroll
    for (int i = 0; i < TM; i++) {
        float4 o;
        o.x = fmaf(acc[i][0], alpha, bv[0]);
        o.y = fmaf(acc[i][1], alpha, bv[1]);
        o.z = fmaf(acc[i][2], alpha, bv[2]);
        o.w = fmaf(acc[i][3], alpha, bv[3]);
        *reinterpret_cast<float4*>(
            &C[(size_t)(m0 + ty * TM + i) * ldc + n0 + tx * TN]) = o;
    }
}

template <bool BNT>
__global__ __launch_bounds__(256)
void gemm_kernel(const float* __restrict__ A, size_t sA,
                 const float* __restrict__ Bm, size_t sB, int ldb,
                 float* __restrict__ C, size_t sC, int ldc,
                 int K, float alpha, const float* __restrict__ bias)
{
    const int b = blockIdx.z;
    gemm_body<BNT>(A + (size_t)b * sA, Bm + (size_t)b * sB,
                   C + (size_t)b * sC, ldb, ldc, K, alpha, bias,
                   blockIdx.y * BM, blockIdx.x * BN);
}

// Merged QKV projection: grid.z = 3*B, z%3 selects {Q,K,V}.
__global__ __launch_bounds__(256)
void qkv_kernel(const float* __restrict__ x,
                const float* __restrict__ Wq, const float* __restrict__ bq,
                const float* __restrict__ Wk, const float* __restrict__ bk,
                const float* __restrict__ Wv, const float* __restrict__ bv,
                float* __restrict__ Sp, float* __restrict__ Ko,
                float* __restrict__ Vo)
{
    const int z = blockIdx.z;
    const int b = z / 3;
    const int w = z - b * 3;
    const float* W  = (w == 0) ? Wq : (w == 1) ? Wk : Wv;
    const float* bi = (w == 0) ? bq : (w == 1) ? bk : bv;
    float* C = (w == 0) ? (Sp + (size_t)b * 2 * LL * DD)
                        : (((w == 1) ? Ko : Vo) + (size_t)b * LL * DD);
    gemm_body<true>(x + (size_t)b * LL * DD, W, C, DD, DD, DD, 1.0f, bi,
                    blockIdx.y * BM, blockIdx.x * BN);
}

// ---------------------------------------------------------------------------
// Fast exp on the fma pipe (no MUFU): exp(x) = 2^(x*log2e), deg-5 poly on
// the fractional part, magic-number round-to-int, exponent add.
// Valid for x in [-87, 87]; rel err ~2.4e-6.
// ---------------------------------------------------------------------------
__device__ __forceinline__ float fexp(float x)
{
    x = fmaxf(x, -87.0f);
    float y = x * 1.4426950408889634f;
    float t = y + 12582912.0f;               // 1.5 * 2^23
    int   i = __float_as_int(t) - 0x4B400000;
    float f = y - (t - 12582912.0f);         // f in [-0.5, 0.5]
    float p = 1.3333558146e-3f;
    p = fmaf(p, f, 9.6181291076e-3f);
    p = fmaf(p, f, 5.5504108664e-2f);
    p = fmaf(p, f, 2.4022650696e-1f);
    p = fmaf(p, f, 6.9314718056e-1f);
    p = fmaf(p, f, 1.0f);
    return __int_as_float(__float_as_int(p) + (i << 23));
}

// ---------------------------------------------------------------------------
// Column softmax over q (dim 1) in 3 kernels, float4 over columns:
//  K1: per (b, q-chunk of 128) online max/sum partials  -> g_pm, g_ps
//  K2: combine 16 partials per column                   -> g_m, g_is
//  K3: A = exp(E - m) * is                              (write pass)
// ---------------------------------------------------------------------------
__global__ __launch_bounds__(256)
void softmax_part(const float* __restrict__ E)
{
    const int b = blockIdx.z, qc = blockIdx.y;
    const int col = (blockIdx.x * 256 + threadIdx.x) * 4;
    const float* p = E + (size_t)b * LL * LL + (size_t)qc * 128 * LL + col;

    float m[4] = {-1e30f, -1e30f, -1e30f, -1e30f};
    float s[4] = {0.f, 0.f, 0.f, 0.f};
#pragma unroll 4
    for (int q = 0; q < 128; q++, p += LL) {
        float4 e = *reinterpret_cast<const float4*>(p);
        float ev[4] = {e.x, e.y, e.z, e.w};
#pragma unroll
        for (int j = 0; j < 4; j++) {
            if (ev[j] > m[j]) {
                s[j] = fmaf(s[j], fexp(m[j] - ev[j]), 1.0f);
                m[j] = ev[j];
            } else {
                s[j] += fexp(ev[j] - m[j]);
            }
        }
    }
    *reinterpret_cast<float4*>(&g_pm[b][qc][col]) =
        make_float4(m[0], m[1], m[2], m[3]);
    *reinterpret_cast<float4*>(&g_ps[b][qc][col]) =
        make_float4(s[0], s[1], s[2], s[3]);
}

__global__ __launch_bounds__(256)
void softmax_combine()
{
    const int b = blockIdx.y;
    const int col = blockIdx.x * 256 + threadIdx.x;
    float m = -1e30f;
#pragma unroll
    for (int c = 0; c < 16; c++) m = fmaxf(m, g_pm[b][c][col]);
    float s = 0.f;
#pragma unroll
    for (int c = 0; c < 16; c++) s += g_ps[b][c][col] * fexp(g_pm[b][c][col] - m);
    g_m[b][col] = m;
    g_is[b][col] = 1.0f / s;
}

__global__ __launch_bounds__(256)
void softmax_write(const float* __restrict__ E, float* __restrict__ Aout)
{
    const int b = blockIdx.z, qc = blockIdx.y;
    const int col = (blockIdx.x * 256 + threadIdx.x) * 4;
    float4 m  = *reinterpret_cast<const float4*>(&g_m[b][col]);
    float4 is = *reinterpret_cast<const float4*>(&g_is[b][col]);
    const size_t off = (size_t)b * LL * LL + (size_t)qc * 128 * LL + col;
    const float* p = E + off;
    float* o = Aout + off;
#pragma unroll 2
    for (int q = 0; q < 128; q++, p += LL, o += LL) {
        float4 e = *reinterpret_cast<const float4*>(p);
        float4 r;
        r.x = fexp(e.x - m.x) * is.x;
        r.y = fexp(e.y - m.y) * is.y;
        r.z = fexp(e.z - m.z) * is.z;
        r.w = fexp(e.w - m.w) * is.w;
        *reinterpret_cast<float4*>(o) = r;
    }
}

// ---------------------------------------------------------------------------
// Launch
// ---------------------------------------------------------------------------
extern "C" void kernel_launch(void* const* d_in, const int* in_sizes, int n_in,
                              void* d_out, int out_size)
{
    const float* x  = (const float*)d_in[0];
    const float* Wq = (const float*)d_in[1];
    const float* bq = (const float*)d_in[2];
    const float* Wk = (const float*)d_in[3];
    const float* bk = (const float*)d_in[4];
    const float* Wv = (const float*)d_in[5];
    const float* bv = (const float*)d_in[6];

    float* out  = (float*)d_out;
    float* Sp   = out;                                  // [B, 2L, D]
    float* Aout = out + (size_t)BB * 2 * LL * DD;       // [B, L, L]

    float *gK, *gV, *gE;
    cudaGetSymbolAddress((void**)&gK, g_K);
    cudaGetSymbolAddress((void**)&gV, g_V);
    cudaGetSymbolAddress((void**)&gE, g_E);

    const size_t sX  = (size_t)LL * DD;
    const size_t sSp = (size_t)2 * LL * DD;
    const size_t sE  = (size_t)LL * LL;

    // QKV projections (merged): Q -> S_p first half, K/V -> scratch
    qkv_kernel<<<dim3(DD / BN, LL / BM, 3 * BB), 256>>>(
        x, Wq, bq, Wk, bk, Wv, bv, Sp, gK, gV);

    // E = Q K^T / 16
    gemm_kernel<true><<<dim3(LL / BN, LL / BM, BB), 256>>>(
        Sp, sSp, gK, sX, DD, gE, sE, LL, DD, 1.0f / 16.0f, nullptr);

    // A = softmax over q (columns of E)
    softmax_part<<<dim3(LL / 1024, 16, BB), 256>>>(gE);
    softmax_combine<<<dim3(LL / 256, BB), 256>>>();
    softmax_write<<<dim3(LL / 1024, 16, BB), 256>>>(gE, Aout);

    // C = A V -> S_p second half
    gemm_kernel<false><<<dim3(DD / BN, LL / BM, BB), 256>>>(
        Aout, sE, gV, sX, DD, Sp + (size_t)LL * DD, sSp, DD,
        LL, 1.0f, nullptr);

    (void)in_sizes; (void)n_in; (void)out_size;
}

// round 4
// speedup vs baseline: 2.0554x; 1.5965x over previous
#include <cuda_runtime.h>
#include <cuda_bf16.h>
#include <cstdint>
#include <cstddef>

// Problem constants
#define BB 8
#define LL 2048
#define DD 256

// ---------------------------------------------------------------------------
// Scratch (__device__ globals; no allocation allowed)
// ---------------------------------------------------------------------------
__device__ float          g_V [(size_t)BB * LL * DD];      // V fp32 (transpose src)
__device__ float          g_E [(size_t)BB * LL * LL];      // E fp32 (softmax src)
__device__ __nv_bfloat16  g_Qh[(size_t)BB * LL * DD];
__device__ __nv_bfloat16  g_Ql[(size_t)BB * LL * DD];
__device__ __nv_bfloat16  g_Kh[(size_t)BB * LL * DD];
__device__ __nv_bfloat16  g_Kl[(size_t)BB * LL * DD];
__device__ __nv_bfloat16  g_VTh[(size_t)BB * DD * LL];     // V^T hi  [b][d][l]
__device__ __nv_bfloat16  g_VTl[(size_t)BB * DD * LL];
__device__ __nv_bfloat16  g_Ah[(size_t)BB * LL * LL];      // A hi/lo for C GEMM
__device__ __nv_bfloat16  g_Al[(size_t)BB * LL * LL];
__device__ float g_pm[BB][16][LL];
__device__ float g_ps[BB][16][LL];
__device__ float g_m [BB][LL];
__device__ float g_is[BB][LL];

// ---------------------------------------------------------------------------
// Helpers
// ---------------------------------------------------------------------------
__device__ __forceinline__ uint32_t smem_u32(const void* p) {
    uint32_t a;
    asm("{ .reg .u64 t; cvta.to.shared.u64 t, %1; cvt.u32.u64 %0, t; }"
        : "=r"(a) : "l"(p));
    return a;
}

#define LDSM4(r, addr)                                                        \
    asm volatile("ldmatrix.sync.aligned.m8n8.x4.shared.b16 {%0,%1,%2,%3}, [%4];" \
                 : "=r"((r)[0]), "=r"((r)[1]), "=r"((r)[2]), "=r"((r)[3])     \
                 : "r"(addr))

#define MMA16816(d, a, b0, b1)                                                \
    asm volatile("mma.sync.aligned.m16n8k16.row.col.f32.bf16.bf16.f32 "       \
                 "{%0,%1,%2,%3}, {%4,%5,%6,%7}, {%8,%9}, {%0,%1,%2,%3};"      \
                 : "+f"((d)[0]), "+f"((d)[1]), "+f"((d)[2]), "+f"((d)[3])     \
                 : "r"((a)[0]), "r"((a)[1]), "r"((a)[2]), "r"((a)[3]),        \
                   "r"(b0), "r"(b1))

// ---------------------------------------------------------------------------
// Split-bf16 tensor-core GEMM via mma.sync:
//   C[m,n] = scale * sum_k A[m,k] * B[n,k]
// A = (Ah, Al), B = (Bh, Bl), bf16 K-major rows; D = Ah*Bh + Ah*Bl + Al*Bh.
// CTA tile 128x128, BK=32, 256 threads (8 warps of 64x32). Single-buffered
// smem; occupancy 2 CTAs/SM hides staging.
// smem row pitch 80B -> ldmatrix 8-row phases conflict-free (r*20 % 32 distinct).
// ---------------------------------------------------------------------------
#define PITCH 80

__global__ __launch_bounds__(256, 2)
void mm_mma(const __nv_bfloat16* __restrict__ Ah, const __nv_bfloat16* __restrict__ Al,
            int lda, size_t sA,
            const __nv_bfloat16* __restrict__ Bh, const __nv_bfloat16* __restrict__ Bl,
            int ldb, size_t sB,
            float* __restrict__ Cf, int ldc, size_t sC,
            int K, float scale)
{
    __shared__ __align__(16) uint8_t sAh[128 * PITCH];
    __shared__ __align__(16) uint8_t sAl[128 * PITCH];
    __shared__ __align__(16) uint8_t sBh[128 * PITCH];
    __shared__ __align__(16) uint8_t sBl[128 * PITCH];

    const int tid = threadIdx.x;
    const int lane = tid & 31;
    const int wm = (tid >> 5) & 1;   // 0..1 : 64 rows each
    const int wn = tid >> 6;         // 0..3 : 32 cols each
    const int b = blockIdx.z;
    const int n0 = blockIdx.x * 128, m0 = blockIdx.y * 128;

    const __nv_bfloat16* pAh = Ah + (size_t)b * sA + (size_t)m0 * lda;
    const __nv_bfloat16* pAl = Al + (size_t)b * sA + (size_t)m0 * lda;
    const __nv_bfloat16* pBh = Bh + (size_t)b * sB + (size_t)n0 * ldb;
    const __nv_bfloat16* pBl = Bl + (size_t)b * sB + (size_t)n0 * ldb;

    // ldmatrix lane bases
    const uint32_t lrow = lane & 15, lhalf = lane >> 4;
    const uint32_t aBaseH = smem_u32(sAh) + (wm * 64 + lrow) * PITCH + lhalf * 16;
    const uint32_t aBaseL = smem_u32(sAl) + (wm * 64 + lrow) * PITCH + lhalf * 16;
    const uint32_t bBaseH = smem_u32(sBh) + (wn * 32 + lrow) * PITCH + lhalf * 16;
    const uint32_t bBaseL = smem_u32(sBl) + (wn * 32 + lrow) * PITCH + lhalf * 16;

    float d[16][4];
#pragma unroll
    for (int i = 0; i < 16; i++)
#pragma unroll
        for (int j = 0; j < 4; j++) d[i][j] = 0.0f;

    const int nch = K / 32;
    for (int kc = 0; kc < nch; kc++) {
        __syncthreads();
        // stage 4 tiles: 128 rows x 32 bf16 (64B) each, 16B chunks
#pragma unroll
        for (int t = 0; t < 2; t++) {
            const int q = tid + t * 256;        // 0..511
            const int row = q >> 2, seg = q & 3;
            const uint32_t so = row * PITCH + seg * 16;
            const size_t goA = (size_t)row * lda + kc * 32 + seg * 8;
            const size_t goB = (size_t)row * ldb + kc * 32 + seg * 8;
            *reinterpret_cast<uint4*>(sAh + so) = *reinterpret_cast<const uint4*>(pAh + goA);
            *reinterpret_cast<uint4*>(sAl + so) = *reinterpret_cast<const uint4*>(pAl + goA);
            *reinterpret_cast<uint4*>(sBh + so) = *reinterpret_cast<const uint4*>(pBh + goB);
            *reinterpret_cast<uint4*>(sBl + so) = *reinterpret_cast<const uint4*>(pBl + goB);
        }
        __syncthreads();

#pragma unroll
        for (int kk = 0; kk < 2; kk++) {
            uint32_t bhf[2][4], blf[2][4];
            LDSM4(bhf[0], bBaseH + kk * 32);
            LDSM4(bhf[1], bBaseH + 16 * PITCH + kk * 32);
            LDSM4(blf[0], bBaseL + kk * 32);
            LDSM4(blf[1], bBaseL + 16 * PITCH + kk * 32);
#pragma unroll
            for (int mt = 0; mt < 4; mt++) {
                uint32_t ah[4], al[4];
                LDSM4(ah, aBaseH + mt * 16 * PITCH + kk * 32);
                LDSM4(al, aBaseL + mt * 16 * PITCH + kk * 32);
#pragma unroll
                for (int g = 0; g < 2; g++) {
#pragma unroll
                    for (int h = 0; h < 2; h++) {
                        float* acc = d[mt * 4 + g * 2 + h];
                        MMA16816(acc, ah, bhf[g][h], bhf[g][h + 2]);
                        MMA16816(acc, ah, blf[g][h], blf[g][h + 2]);
                        MMA16816(acc, al, bhf[g][h], bhf[g][h + 2]);
                    }
                }
            }
        }
    }

    // epilogue
    float* Cb = Cf + (size_t)b * sC;
#pragma unroll
    for (int mt = 0; mt < 4; mt++) {
#pragma unroll
        for (int ni = 0; ni < 4; ni++) {
            const float* acc = d[mt * 4 + ni];
            const int row = m0 + wm * 64 + mt * 16 + (lane >> 2);
            const int col = n0 + wn * 32 + ni * 8 + (lane & 3) * 2;
            float2 v0 = {acc[0] * scale, acc[1] * scale};
            float2 v1 = {acc[2] * scale, acc[3] * scale};
            *reinterpret_cast<float2*>(&Cb[(size_t)row * ldc + col]) = v0;
            *reinterpret_cast<float2*>(&Cb[(size_t)(row + 8) * ldc + col]) = v1;
        }
    }
}

// ---------------------------------------------------------------------------
// QKV projection (fp32 FFMA SGEMM; K=256 so cheap).
// Writes: Q -> Sp fp32 + (Qh,Ql); K -> (Kh,Kl) only; V -> fp32 scratch.
// ---------------------------------------------------------------------------
#define BM 128
#define BN 64
#define BK 16
#define TM 8
#define TN 4

__device__ __forceinline__ void bf16split4(const float* v, uint32_t& hi2, uint32_t& hi2b,
                                           uint32_t& lo2, uint32_t& lo2b)
{
    __nv_bfloat16 h[4], l[4];
#pragma unroll
    for (int j = 0; j < 4; j++) {
        h[j] = __float2bfloat16(v[j]);
        l[j] = __float2bfloat16(v[j] - __bfloat162float(h[j]));
    }
    hi2  = (uint32_t)*(uint16_t*)&h[0] | ((uint32_t)*(uint16_t*)&h[1] << 16);
    hi2b = (uint32_t)*(uint16_t*)&h[2] | ((uint32_t)*(uint16_t*)&h[3] << 16);
    lo2  = (uint32_t)*(uint16_t*)&l[0] | ((uint32_t)*(uint16_t*)&l[1] << 16);
    lo2b = (uint32_t)*(uint16_t*)&l[2] | ((uint32_t)*(uint16_t*)&l[3] << 16);
}

__global__ __launch_bounds__(256)
void qkv_kernel(const float* __restrict__ x,
                const float* __restrict__ Wq, const float* __restrict__ bq,
                const float* __restrict__ Wk, const float* __restrict__ bk,
                const float* __restrict__ Wv, const float* __restrict__ bv,
                float* __restrict__ Sp, float* __restrict__ Vo)
{
    __shared__ float As[BK][BM];
    __shared__ float Bs[BK][BN];

    const int z = blockIdx.z;
    const int b = z / 3;
    const int w = z - b * 3;
    const float* W  = (w == 0) ? Wq : (w == 1) ? Wk : Wv;
    const float* bi = (w == 0) ? bq : (w == 1) ? bk : bv;
    const float* A  = x + (size_t)b * LL * DD;

    const int n0 = blockIdx.x * BN;
    const int m0 = blockIdx.y * BM;
    const int tid = threadIdx.x;
    const int tx = tid & 15, ty = tid >> 4;

    float acc[TM][TN];
#pragma unroll
    for (int i = 0; i < TM; i++)
#pragma unroll
        for (int j = 0; j < TN; j++) acc[i][j] = 0.0f;

    for (int k0 = 0; k0 < DD; k0 += BK) {
#pragma unroll
        for (int l = 0; l < 2; l++) {
            int f = tid + l * 256, row = f >> 2, kq = (f & 3) * 4;
            float4 v = *reinterpret_cast<const float4*>(
                &A[(size_t)(m0 + row) * DD + k0 + kq]);
            As[kq + 0][row] = v.x; As[kq + 1][row] = v.y;
            As[kq + 2][row] = v.z; As[kq + 3][row] = v.w;
        }
        {
            int n = tid >> 2, kq = (tid & 3) * 4;
            float4 v = *reinterpret_cast<const float4*>(
                &W[(size_t)(n0 + n) * DD + k0 + kq]);
            Bs[kq + 0][n] = v.x; Bs[kq + 1][n] = v.y;
            Bs[kq + 2][n] = v.z; Bs[kq + 3][n] = v.w;
        }
        __syncthreads();
#pragma unroll
        for (int kk = 0; kk < BK; kk++) {
            float a[TM], bvv[TN];
            float4 a0 = *reinterpret_cast<const float4*>(&As[kk][ty * TM]);
            float4 a1 = *reinterpret_cast<const float4*>(&As[kk][ty * TM + 4]);
            a[0]=a0.x; a[1]=a0.y; a[2]=a0.z; a[3]=a0.w;
            a[4]=a1.x; a[5]=a1.y; a[6]=a1.z; a[7]=a1.w;
            float4 b0 = *reinterpret_cast<const float4*>(&Bs[kk][tx * TN]);
            bvv[0]=b0.x; bvv[1]=b0.y; bvv[2]=b0.z; bvv[3]=b0.w;
#pragma unroll
            for (int i = 0; i < TM; i++)
#pragma unroll
                for (int j = 0; j < TN; j++)
                    acc[i][j] = fmaf(a[i], bvv[j], acc[i][j]);
        }
        __syncthreads();
    }

    float4 bb = *reinterpret_cast<const float4*>(&bi[n0 + tx * TN]);
    const float bvv[4] = {bb.x, bb.y, bb.z, bb.w};

    float*        Cfp = (w == 0) ? (Sp + (size_t)b * 2 * LL * DD)
                     : (w == 2) ? (Vo + (size_t)b * LL * DD) : nullptr;
    __nv_bfloat16* Ch = (w == 0) ? (g_Qh + (size_t)b * LL * DD)
                     : (w == 1) ? (g_Kh + (size_t)b * LL * DD) : nullptr;
    __nv_bfloat16* Cl = (w == 0) ? (g_Ql + (size_t)b * LL * DD)
                     : (w == 1) ? (g_Kl + (size_t)b * LL * DD) : nullptr;

#pragma unroll
    for (int i = 0; i < TM; i++) {
        float v[4];
#pragma unroll
        for (int j = 0; j < 4; j++) v[j] = acc[i][j] + bvv[j];
        const size_t row = (size_t)(m0 + ty * TM + i);
        const int col = n0 + tx * TN;
        if (Cfp) {
            float4 o = {v[0], v[1], v[2], v[3]};
            *reinterpret_cast<float4*>(&Cfp[row * DD + col]) = o;
        }
        if (Ch) {
            uint32_t h0, h1, l0, l1;
            bf16split4(v, h0, h1, l0, l1);
            uint2 hh = {h0, h1}, ll = {l0, l1};
            *reinterpret_cast<uint2*>(&Ch[row * DD + col]) = hh;
            *reinterpret_cast<uint2*>(&Cl[row * DD + col]) = ll;
        }
    }
}

// ---------------------------------------------------------------------------
// V [b][l][d] fp32 -> VT hi/lo bf16 [b][d][l]
// ---------------------------------------------------------------------------
__global__ __launch_bounds__(256)
void vtrans_kernel(const float* __restrict__ V)
{
    __shared__ float t[32][33];
    const int b = blockIdx.z;
    const int l0 = blockIdx.x * 32, d0 = blockIdx.y * 32;
    const int tx = threadIdx.x & 31, ty = threadIdx.x >> 5;  // 32 x 8

    const float* Vb = V + (size_t)b * LL * DD;
#pragma unroll
    for (int i = 0; i < 4; i++)
        t[ty + i * 8][tx] = Vb[(size_t)(l0 + ty + i * 8) * DD + d0 + tx];
    __syncthreads();

    __nv_bfloat16* Th = g_VTh + (size_t)b * DD * LL;
    __nv_bfloat16* Tl = g_VTl + (size_t)b * DD * LL;
#pragma unroll
    for (int i = 0; i < 4; i++) {
        float v = t[tx][ty + i * 8];
        __nv_bfloat16 h = __float2bfloat16(v);
        __nv_bfloat16 l = __float2bfloat16(v - __bfloat162float(h));
        Th[(size_t)(d0 + ty + i * 8) * LL + l0 + tx] = h;
        Tl[(size_t)(d0 + ty + i * 8) * LL + l0 + tx] = l;
    }
}

// ---------------------------------------------------------------------------
// Fast exp on the fma pipe
// ---------------------------------------------------------------------------
__device__ __forceinline__ float fexp(float x)
{
    x = fmaxf(x, -87.0f);
    float y = x * 1.4426950408889634f;
    float t = y + 12582912.0f;
    int   i = __float_as_int(t) - 0x4B400000;
    float f = y - (t - 12582912.0f);
    float p = 1.3333558146e-3f;
    p = fmaf(p, f, 9.6181291076e-3f);
    p = fmaf(p, f, 5.5504108664e-2f);
    p = fmaf(p, f, 2.4022650696e-1f);
    p = fmaf(p, f, 6.9314718056e-1f);
    p = fmaf(p, f, 1.0f);
    return __int_as_float(__float_as_int(p) + (i << 23));
}

// ---------------------------------------------------------------------------
// Column softmax (over q) — 3 kernels. softmax_write also emits A hi/lo bf16.
// ---------------------------------------------------------------------------
__global__ __launch_bounds__(256)
void softmax_part(const float* __restrict__ E)
{
    const int b = blockIdx.z, qc = blockIdx.y;
    const int col = (blockIdx.x * 256 + threadIdx.x) * 4;
    const float* p = E + (size_t)b * LL * LL + (size_t)qc * 128 * LL + col;

    float m[4] = {-1e30f, -1e30f, -1e30f, -1e30f};
    float s[4] = {0.f, 0.f, 0.f, 0.f};
#pragma unroll 4
    for (int q = 0; q < 128; q++, p += LL) {
        float4 e = *reinterpret_cast<const float4*>(p);
        float ev[4] = {e.x, e.y, e.z, e.w};
#pragma unroll
        for (int j = 0; j < 4; j++) {
            if (ev[j] > m[j]) {
                s[j] = fmaf(s[j], fexp(m[j] - ev[j]), 1.0f);
                m[j] = ev[j];
            } else {
                s[j] += fexp(ev[j] - m[j]);
            }
        }
    }
    *reinterpret_cast<float4*>(&g_pm[b][qc][col]) = make_float4(m[0], m[1], m[2], m[3]);
    *reinterpret_cast<float4*>(&g_ps[b][qc][col]) = make_float4(s[0], s[1], s[2], s[3]);
}

__global__ __launch_bounds__(256)
void softmax_combine()
{
    const int b = blockIdx.y;
    const int col = blockIdx.x * 256 + threadIdx.x;
    float m = -1e30f;
#pragma unroll
    for (int c = 0; c < 16; c++) m = fmaxf(m, g_pm[b][c][col]);
    float s = 0.f;
#pragma unroll
    for (int c = 0; c < 16; c++) s += g_ps[b][c][col] * fexp(g_pm[b][c][col] - m);
    g_m[b][col] = m;
    g_is[b][col] = 1.0f / s;
}

__global__ __launch_bounds__(256)
void softmax_write(const float* __restrict__ E, float* __restrict__ Aout)
{
    const int b = blockIdx.z, qc = blockIdx.y;
    const int col = (blockIdx.x * 256 + threadIdx.x) * 4;
    float4 m  = *reinterpret_cast<const float4*>(&g_m[b][col]);
    float4 is = *reinterpret_cast<const float4*>(&g_is[b][col]);
    const size_t off = (size_t)b * LL * LL + (size_t)qc * 128 * LL + col;
    const float* p = E + off;
    float* o = Aout + off;
    __nv_bfloat16* oh = g_Ah + off;
    __nv_bfloat16* ol = g_Al + off;
#pragma unroll 2
    for (int q = 0; q < 128; q++, p += LL, o += LL, oh += LL, ol += LL) {
        float4 e = *reinterpret_cast<const float4*>(p);
        float r[4];
        r[0] = fexp(e.x - m.x) * is.x;
        r[1] = fexp(e.y - m.y) * is.y;
        r[2] = fexp(e.z - m.z) * is.z;
        r[3] = fexp(e.w - m.w) * is.w;
        *reinterpret_cast<float4*>(o) = make_float4(r[0], r[1], r[2], r[3]);
        uint32_t h0, h1, l0, l1;
        bf16split4(r, h0, h1, l0, l1);
        uint2 hh = {h0, h1}, ll = {l0, l1};
        *reinterpret_cast<uint2*>(oh) = hh;
        *reinterpret_cast<uint2*>(ol) = ll;
    }
}

// ---------------------------------------------------------------------------
// Launch
// ---------------------------------------------------------------------------
extern "C" void kernel_launch(void* const* d_in, const int* in_sizes, int n_in,
                              void* d_out, int out_size)
{
    const float* x  = (const float*)d_in[0];
    const float* Wq = (const float*)d_in[1];
    const float* bq = (const float*)d_in[2];
    const float* Wk = (const float*)d_in[3];
    const float* bk = (const float*)d_in[4];
    const float* Wv = (const float*)d_in[5];
    const float* bv = (const float*)d_in[6];

    float* out  = (float*)d_out;
    float* Sp   = out;                                  // [B, 2L, D]
    float* Aout = out + (size_t)BB * 2 * LL * DD;       // [B, L, L]

    float *gV, *gE;
    __nv_bfloat16 *gQh, *gQl, *gKh, *gKl, *gVTh, *gVTl, *gAh, *gAl;
    cudaGetSymbolAddress((void**)&gV,  g_V);
    cudaGetSymbolAddress((void**)&gE,  g_E);
    cudaGetSymbolAddress((void**)&gQh, g_Qh);
    cudaGetSymbolAddress((void**)&gQl, g_Ql);
    cudaGetSymbolAddress((void**)&gKh, g_Kh);
    cudaGetSymbolAddress((void**)&gKl, g_Kl);
    cudaGetSymbolAddress((void**)&gVTh, g_VTh);
    cudaGetSymbolAddress((void**)&gVTl, g_VTl);
    cudaGetSymbolAddress((void**)&gAh, g_Ah);
    cudaGetSymbolAddress((void**)&gAl, g_Al);

    const size_t sX  = (size_t)LL * DD;
    const size_t sSp = (size_t)2 * LL * DD;
    const size_t sE  = (size_t)LL * LL;

    // 1) QKV: Q -> Sp fp32 + hi/lo, K -> hi/lo, V -> fp32 scratch
    qkv_kernel<<<dim3(DD / BN, LL / BM, 3 * BB), 256>>>(
        x, Wq, bq, Wk, bk, Wv, bv, Sp, gV);

    // 2) V -> VT hi/lo
    vtrans_kernel<<<dim3(LL / 32, DD / 32, BB), 256>>>(gV);

    // 3) E = Q K^T / 16  (mma.sync split-bf16)
    mm_mma<<<dim3(LL / 128, LL / 128, BB), 256>>>(
        gQh, gQl, DD, sX, gKh, gKl, DD, sX,
        gE, LL, sE, DD, 1.0f / 16.0f);

    // 4) softmax over q
    softmax_part<<<dim3(LL / 1024, 16, BB), 256>>>(gE);
    softmax_combine<<<dim3(LL / 256, BB), 256>>>();
    softmax_write<<<dim3(LL / 1024, 16, BB), 256>>>(gE, Aout);

    // 5) C = A V -> Sp second half  (mma.sync split-bf16, B = V^T)
    mm_mma<<<dim3(DD / 128, LL / 128, BB), 256>>>(
        gAh, gAl, LL, sE, gVTh, gVTl, LL, (size_t)DD * LL,
        Sp + (size_t)LL * DD, DD, sSp, LL, 1.0f);

    (void)in_sizes; (void)n_in; (void)out_size;
}

// round 5
// speedup vs baseline: 2.5657x; 1.2483x over previous
#include <cuda_runtime.h>
#include <cuda_bf16.h>
#include <cstdint>
#include <cstddef>

// Problem constants
#define BB 8
#define LL 2048
#define DD 256

// ---------------------------------------------------------------------------
// Scratch (__device__ globals; no allocation allowed)
// ---------------------------------------------------------------------------
__device__ float          g_V [(size_t)BB * LL * DD];      // V fp32 (transpose src)
__device__ float          g_E [(size_t)BB * LL * LL];      // E fp32 (softmax src)
__device__ __nv_bfloat16  g_Qh[(size_t)BB * LL * DD];
__device__ __nv_bfloat16  g_Ql[(size_t)BB * LL * DD];
__device__ __nv_bfloat16  g_Kh[(size_t)BB * LL * DD];
__device__ __nv_bfloat16  g_Kl[(size_t)BB * LL * DD];
__device__ __nv_bfloat16  g_VTh[(size_t)BB * DD * LL];     // V^T hi  [b][d][l]
__device__ __nv_bfloat16  g_VTl[(size_t)BB * DD * LL];
__device__ float g_pm[BB][16][LL];
__device__ float g_ps[BB][16][LL];
__device__ float g_m [BB][LL];
__device__ float g_is[BB][LL];

// ---------------------------------------------------------------------------
// Helpers
// ---------------------------------------------------------------------------
__device__ __forceinline__ uint32_t smem_u32(const void* p) {
    uint32_t a;
    asm("{ .reg .u64 t; cvta.to.shared.u64 t, %1; cvt.u32.u64 %0, t; }"
        : "=r"(a) : "l"(p));
    return a;
}

#define LDSM4(r, addr)                                                        \
    asm volatile("ldmatrix.sync.aligned.m8n8.x4.shared.b16 {%0,%1,%2,%3}, [%4];" \
                 : "=r"((r)[0]), "=r"((r)[1]), "=r"((r)[2]), "=r"((r)[3])     \
                 : "r"(addr))

#define MMA16816(d, a, b0, b1)                                                \
    asm volatile("mma.sync.aligned.m16n8k16.row.col.f32.bf16.bf16.f32 "       \
                 "{%0,%1,%2,%3}, {%4,%5,%6,%7}, {%8,%9}, {%0,%1,%2,%3};"      \
                 : "+f"((d)[0]), "+f"((d)[1]), "+f"((d)[2]), "+f"((d)[3])     \
                 : "r"((a)[0]), "r"((a)[1]), "r"((a)[2]), "r"((a)[3]),        \
                   "r"(b0), "r"(b1))

// Fast exp on the fma pipe (no MUFU); rel err ~2.4e-6, valid x <= ~87
__device__ __forceinline__ float fexp(float x)
{
    x = fmaxf(x, -87.0f);
    float y = x * 1.4426950408889634f;
    float t = y + 12582912.0f;
    int   i = __float_as_int(t) - 0x4B400000;
    float f = y - (t - 12582912.0f);
    float p = 1.3333558146e-3f;
    p = fmaf(p, f, 9.6181291076e-3f);
    p = fmaf(p, f, 5.5504108664e-2f);
    p = fmaf(p, f, 2.4022650696e-1f);
    p = fmaf(p, f, 6.9314718056e-1f);
    p = fmaf(p, f, 1.0f);
    return __int_as_float(__float_as_int(p) + (i << 23));
}

__device__ __forceinline__ void bf16split4(const float* v, uint32_t& hi2, uint32_t& hi2b,
                                           uint32_t& lo2, uint32_t& lo2b)
{
    __nv_bfloat16 h[4], l[4];
#pragma unroll
    for (int j = 0; j < 4; j++) {
        h[j] = __float2bfloat16(v[j]);
        l[j] = __float2bfloat16(v[j] - __bfloat162float(h[j]));
    }
    hi2  = (uint32_t)*(uint16_t*)&h[0] | ((uint32_t)*(uint16_t*)&h[1] << 16);
    hi2b = (uint32_t)*(uint16_t*)&h[2] | ((uint32_t)*(uint16_t*)&h[3] << 16);
    lo2  = (uint32_t)*(uint16_t*)&l[0] | ((uint32_t)*(uint16_t*)&l[1] << 16);
    lo2b = (uint32_t)*(uint16_t*)&l[2] | ((uint32_t)*(uint16_t*)&l[3] << 16);
}

// ---------------------------------------------------------------------------
// Split-bf16 tensor-core GEMM via mma.sync:
//   C[m,n] = scale * sum_k A[m,k] * B[n,k]
// SPLIT_A=false: A given as (Ah, Al) bf16 rows.
// SPLIT_A=true : A given as fp32 (Afp); hi/lo split done during smem staging.
// FUSE_SM=true : also emit per-tile column (over m) softmax partials into
//                g_pm/g_ps[b][blockIdx.y][col] (used by the E GEMM).
// CTA tile 128x128, BK=32, 256 threads (8 warps of 64x32).
// smem row pitch 80B -> ldmatrix 8-row phases conflict-free.
// ---------------------------------------------------------------------------
#define PITCH 80

template <bool SPLIT_A, bool FUSE_SM>
__global__ __launch_bounds__(256, 2)
void mm_mma(const __nv_bfloat16* __restrict__ Ah, const __nv_bfloat16* __restrict__ Al,
            const float* __restrict__ Afp,
            int lda, size_t sA,
            const __nv_bfloat16* __restrict__ Bh, const __nv_bfloat16* __restrict__ Bl,
            int ldb, size_t sB,
            float* __restrict__ Cf, int ldc, size_t sC,
            int K, float scale)
{
    __shared__ __align__(16) uint8_t sAh[128 * PITCH];
    __shared__ __align__(16) uint8_t sAl[128 * PITCH];
    __shared__ __align__(16) uint8_t sBh[128 * PITCH];
    __shared__ __align__(16) uint8_t sBl[128 * PITCH];

    const int tid = threadIdx.x;
    const int lane = tid & 31;
    const int wm = (tid >> 5) & 1;   // 0..1 : 64 rows each
    const int wn = tid >> 6;         // 0..3 : 32 cols each
    const int b = blockIdx.z;
    const int n0 = blockIdx.x * 128, m0 = blockIdx.y * 128;

    const __nv_bfloat16* pAh = SPLIT_A ? nullptr : (Ah + (size_t)b * sA + (size_t)m0 * lda);
    const __nv_bfloat16* pAl = SPLIT_A ? nullptr : (Al + (size_t)b * sA + (size_t)m0 * lda);
    const float*         pAf = SPLIT_A ? (Afp + (size_t)b * sA + (size_t)m0 * lda) : nullptr;
    const __nv_bfloat16* pBh = Bh + (size_t)b * sB + (size_t)n0 * ldb;
    const __nv_bfloat16* pBl = Bl + (size_t)b * sB + (size_t)n0 * ldb;

    // ldmatrix lane bases
    const uint32_t lrow = lane & 15, lhalf = lane >> 4;
    const uint32_t aBaseH = smem_u32(sAh) + (wm * 64 + lrow) * PITCH + lhalf * 16;
    const uint32_t aBaseL = smem_u32(sAl) + (wm * 64 + lrow) * PITCH + lhalf * 16;
    const uint32_t bBaseH = smem_u32(sBh) + (wn * 32 + lrow) * PITCH + lhalf * 16;
    const uint32_t bBaseL = smem_u32(sBl) + (wn * 32 + lrow) * PITCH + lhalf * 16;

    float d[16][4];
#pragma unroll
    for (int i = 0; i < 16; i++)
#pragma unroll
        for (int j = 0; j < 4; j++) d[i][j] = 0.0f;

    const int nch = K / 32;
    for (int kc = 0; kc < nch; kc++) {
        __syncthreads();
        // --- stage A tiles
        if constexpr (SPLIT_A) {
            // 128 rows x 32 fp32 = 1024 float4; split to bf16 hi/lo on the fly
#pragma unroll
            for (int t = 0; t < 4; t++) {
                const int q = tid + t * 256;          // 0..1023
                const int row = q >> 3, seg = q & 7;  // seg: float4 index
                float4 v4 = *reinterpret_cast<const float4*>(
                    pAf + (size_t)row * lda + kc * 32 + seg * 4);
                float v[4] = {v4.x, v4.y, v4.z, v4.w};
                uint32_t h0, h1, l0, l1;
                bf16split4(v, h0, h1, l0, l1);
                const uint32_t so = row * PITCH + seg * 8;
                *reinterpret_cast<uint2*>(sAh + so) = make_uint2(h0, h1);
                *reinterpret_cast<uint2*>(sAl + so) = make_uint2(l0, l1);
            }
        } else {
#pragma unroll
            for (int t = 0; t < 2; t++) {
                const int q = tid + t * 256;
                const int row = q >> 2, seg = q & 3;
                const uint32_t so = row * PITCH + seg * 16;
                const size_t go = (size_t)row * lda + kc * 32 + seg * 8;
                *reinterpret_cast<uint4*>(sAh + so) = *reinterpret_cast<const uint4*>(pAh + go);
                *reinterpret_cast<uint4*>(sAl + so) = *reinterpret_cast<const uint4*>(pAl + go);
            }
        }
        // --- stage B tiles (always bf16)
#pragma unroll
        for (int t = 0; t < 2; t++) {
            const int q = tid + t * 256;
            const int row = q >> 2, seg = q & 3;
            const uint32_t so = row * PITCH + seg * 16;
            const size_t go = (size_t)row * ldb + kc * 32 + seg * 8;
            *reinterpret_cast<uint4*>(sBh + so) = *reinterpret_cast<const uint4*>(pBh + go);
            *reinterpret_cast<uint4*>(sBl + so) = *reinterpret_cast<const uint4*>(pBl + go);
        }
        __syncthreads();

#pragma unroll
        for (int kk = 0; kk < 2; kk++) {
            uint32_t bhf[2][4], blf[2][4];
            LDSM4(bhf[0], bBaseH + kk * 32);
            LDSM4(bhf[1], bBaseH + 16 * PITCH + kk * 32);
            LDSM4(blf[0], bBaseL + kk * 32);
            LDSM4(blf[1], bBaseL + 16 * PITCH + kk * 32);
#pragma unroll
            for (int mt = 0; mt < 4; mt++) {
                uint32_t ah[4], al[4];
                LDSM4(ah, aBaseH + mt * 16 * PITCH + kk * 32);
                LDSM4(al, aBaseL + mt * 16 * PITCH + kk * 32);
#pragma unroll
                for (int g = 0; g < 2; g++) {
#pragma unroll
                    for (int h = 0; h < 2; h++) {
                        float* acc = d[mt * 4 + g * 2 + h];
                        MMA16816(acc, ah, bhf[g][h], bhf[g][h + 2]);
                        MMA16816(acc, ah, blf[g][h], blf[g][h + 2]);
                        MMA16816(acc, al, bhf[g][h], bhf[g][h + 2]);
                    }
                }
            }
        }
    }

    // scale in place
#pragma unroll
    for (int i = 0; i < 16; i++)
#pragma unroll
        for (int j = 0; j < 4; j++) d[i][j] *= scale;

    // write C
    float* Cb = Cf + (size_t)b * sC;
#pragma unroll
    for (int mt = 0; mt < 4; mt++) {
#pragma unroll
        for (int ni = 0; ni < 4; ni++) {
            const float* acc = d[mt * 4 + ni];
            const int row = m0 + wm * 64 + mt * 16 + (lane >> 2);
            const int col = n0 + wn * 32 + ni * 8 + (lane & 3) * 2;
            float2 v0 = {acc[0], acc[1]};
            float2 v1 = {acc[2], acc[3]};
            *reinterpret_cast<float2*>(&Cb[(size_t)row * ldc + col]) = v0;
            *reinterpret_cast<float2*>(&Cb[(size_t)(row + 8) * ldc + col]) = v1;
        }
    }

    // fused per-tile column softmax partials (max / sumexp over the 128 rows)
    if constexpr (FUSE_SM) {
        __shared__ float sMx[2][128];
        __shared__ float sSm[2][128];
#pragma unroll
        for (int ni = 0; ni < 4; ni++) {
#pragma unroll
            for (int p = 0; p < 2; p++) {
                float mx = -1e30f;
#pragma unroll
                for (int mt = 0; mt < 4; mt++)
                    mx = fmaxf(mx, fmaxf(d[mt * 4 + ni][p], d[mt * 4 + ni][p + 2]));
                float sm = 0.0f;
#pragma unroll
                for (int mt = 0; mt < 4; mt++)
                    sm += fexp(d[mt * 4 + ni][p] - mx) + fexp(d[mt * 4 + ni][p + 2] - mx);
                // reduce across the 8 lanes sharing this column (stride-4 groups)
#pragma unroll
                for (int off = 4; off < 32; off <<= 1) {
                    float omx = __shfl_xor_sync(0xFFFFFFFFu, mx, off);
                    float osm = __shfl_xor_sync(0xFFFFFFFFu, sm, off);
                    float nm = fmaxf(mx, omx);
                    sm = sm * fexp(mx - nm) + osm * fexp(omx - nm);
                    mx = nm;
                }
                if ((lane >> 2) == 0) {
                    const int c = wn * 32 + ni * 8 + (lane & 3) * 2 + p;
                    sMx[wm][c] = mx;
                    sSm[wm][c] = sm;
                }
            }
        }
        __syncthreads();
        if (tid < 128) {
            float m0v = sMx[0][tid], m1v = sMx[1][tid];
            float nm = fmaxf(m0v, m1v);
            float s = sSm[0][tid] * fexp(m0v - nm) + sSm[1][tid] * fexp(m1v - nm);
            g_pm[b][blockIdx.y][n0 + tid] = nm;
            g_ps[b][blockIdx.y][n0 + tid] = s;
        }
    }
}

// ---------------------------------------------------------------------------
// QKV projection (fp32 FFMA SGEMM; K=256).
// Writes: Q -> Sp fp32 + (Qh,Ql); K -> (Kh,Kl) only; V -> fp32 scratch.
// ---------------------------------------------------------------------------
#define BM 128
#define BN 64
#define BK 16
#define TM 8
#define TN 4

__global__ __launch_bounds__(256)
void qkv_kernel(const float* __restrict__ x,
                const float* __restrict__ Wq, const float* __restrict__ bq,
                const float* __restrict__ Wk, const float* __restrict__ bk,
                const float* __restrict__ Wv, const float* __restrict__ bv,
                float* __restrict__ Sp, float* __restrict__ Vo)
{
    __shared__ float As[BK][BM];
    __shared__ float Bs[BK][BN];

    const int z = blockIdx.z;
    const int b = z / 3;
    const int w = z - b * 3;
    const float* W  = (w == 0) ? Wq : (w == 1) ? Wk : Wv;
    const float* bi = (w == 0) ? bq : (w == 1) ? bk : bv;
    const float* A  = x + (size_t)b * LL * DD;

    const int n0 = blockIdx.x * BN;
    const int m0 = blockIdx.y * BM;
    const int tid = threadIdx.x;
    const int tx = tid & 15, ty = tid >> 4;

    float acc[TM][TN];
#pragma unroll
    for (int i = 0; i < TM; i++)
#pragma unroll
        for (int j = 0; j < TN; j++) acc[i][j] = 0.0f;

    for (int k0 = 0; k0 < DD; k0 += BK) {
#pragma unroll
        for (int l = 0; l < 2; l++) {
            int f = tid + l * 256, row = f >> 2, kq = (f & 3) * 4;
            float4 v = *reinterpret_cast<const float4*>(
                &A[(size_t)(m0 + row) * DD + k0 + kq]);
            As[kq + 0][row] = v.x; As[kq + 1][row] = v.y;
            As[kq + 2][row] = v.z; As[kq + 3][row] = v.w;
        }
        {
            int n = tid >> 2, kq = (tid & 3) * 4;
            float4 v = *reinterpret_cast<const float4*>(
                &W[(size_t)(n0 + n) * DD + k0 + kq]);
            Bs[kq + 0][n] = v.x; Bs[kq + 1][n] = v.y;
            Bs[kq + 2][n] = v.z; Bs[kq + 3][n] = v.w;
        }
        __syncthreads();
#pragma unroll
        for (int kk = 0; kk < BK; kk++) {
            float a[TM], bvv[TN];
            float4 a0 = *reinterpret_cast<const float4*>(&As[kk][ty * TM]);
            float4 a1 = *reinterpret_cast<const float4*>(&As[kk][ty * TM + 4]);
            a[0]=a0.x; a[1]=a0.y; a[2]=a0.z; a[3]=a0.w;
            a[4]=a1.x; a[5]=a1.y; a[6]=a1.z; a[7]=a1.w;
            float4 b0 = *reinterpret_cast<const float4*>(&Bs[kk][tx * TN]);
            bvv[0]=b0.x; bvv[1]=b0.y; bvv[2]=b0.z; bvv[3]=b0.w;
#pragma unroll
            for (int i = 0; i < TM; i++)
#pragma unroll
                for (int j = 0; j < TN; j++)
                    acc[i][j] = fmaf(a[i], bvv[j], acc[i][j]);
        }
        __syncthreads();
    }

    float4 bb = *reinterpret_cast<const float4*>(&bi[n0 + tx * TN]);
    const float bvv[4] = {bb.x, bb.y, bb.z, bb.w};

    float*        Cfp = (w == 0) ? (Sp + (size_t)b * 2 * LL * DD)
                     : (w == 2) ? (Vo + (size_t)b * LL * DD) : nullptr;
    __nv_bfloat16* Ch = (w == 0) ? (g_Qh + (size_t)b * LL * DD)
                     : (w == 1) ? (g_Kh + (size_t)b * LL * DD) : nullptr;
    __nv_bfloat16* Cl = (w == 0) ? (g_Ql + (size_t)b * LL * DD)
                     : (w == 1) ? (g_Kl + (size_t)b * LL * DD) : nullptr;

#pragma unroll
    for (int i = 0; i < TM; i++) {
        float v[4];
#pragma unroll
        for (int j = 0; j < 4; j++) v[j] = acc[i][j] + bvv[j];
        const size_t row = (size_t)(m0 + ty * TM + i);
        const int col = n0 + tx * TN;
        if (Cfp) {
            float4 o = {v[0], v[1], v[2], v[3]};
            *reinterpret_cast<float4*>(&Cfp[row * DD + col]) = o;
        }
        if (Ch) {
            uint32_t h0, h1, l0, l1;
            bf16split4(v, h0, h1, l0, l1);
            uint2 hh = {h0, h1}, ll = {l0, l1};
            *reinterpret_cast<uint2*>(&Ch[row * DD + col]) = hh;
            *reinterpret_cast<uint2*>(&Cl[row * DD + col]) = ll;
        }
    }
}

// ---------------------------------------------------------------------------
// V [b][l][d] fp32 -> VT hi/lo bf16 [b][d][l]
// ---------------------------------------------------------------------------
__global__ __launch_bounds__(256)
void vtrans_kernel(const float* __restrict__ V)
{
    __shared__ float t[32][33];
    const int b = blockIdx.z;
    const int l0 = blockIdx.x * 32, d0 = blockIdx.y * 32;
    const int tx = threadIdx.x & 31, ty = threadIdx.x >> 5;  // 32 x 8

    const float* Vb = V + (size_t)b * LL * DD;
#pragma unroll
    for (int i = 0; i < 4; i++)
        t[ty + i * 8][tx] = Vb[(size_t)(l0 + ty + i * 8) * DD + d0 + tx];
    __syncthreads();

    __nv_bfloat16* Th = g_VTh + (size_t)b * DD * LL;
    __nv_bfloat16* Tl = g_VTl + (size_t)b * DD * LL;
#pragma unroll
    for (int i = 0; i < 4; i++) {
        float v = t[tx][ty + i * 8];
        __nv_bfloat16 h = __float2bfloat16(v);
        __nv_bfloat16 l = __float2bfloat16(v - __bfloat162float(h));
        Th[(size_t)(d0 + ty + i * 8) * LL + l0 + tx] = h;
        Tl[(size_t)(d0 + ty + i * 8) * LL + l0 + tx] = l;
    }
}

// ---------------------------------------------------------------------------
// Softmax combine (16 partials per column) + write pass
// ---------------------------------------------------------------------------
__global__ __launch_bounds__(256)
void softmax_combine()
{
    const int b = blockIdx.y;
    const int col = blockIdx.x * 256 + threadIdx.x;
    float m = -1e30f;
#pragma unroll
    for (int c = 0; c < 16; c++) m = fmaxf(m, g_pm[b][c][col]);
    float s = 0.f;
#pragma unroll
    for (int c = 0; c < 16; c++) s += g_ps[b][c][col] * fexp(g_pm[b][c][col] - m);
    g_m[b][col] = m;
    g_is[b][col] = 1.0f / s;
}

__global__ __launch_bounds__(256)
void softmax_write(const float* __restrict__ E, float* __restrict__ Aout)
{
    const int b = blockIdx.z, qc = blockIdx.y;           // qc: 64-row chunk
    const int col = (blockIdx.x * 256 + threadIdx.x) * 4;
    float4 m  = *reinterpret_cast<const float4*>(&g_m[b][col]);
    float4 is = *reinterpret_cast<const float4*>(&g_is[b][col]);
    const size_t off = (size_t)b * LL * LL + (size_t)qc * 64 * LL + col;
    const float* p = E + off;
    float* o = Aout + off;
#pragma unroll 4
    for (int q = 0; q < 64; q++, p += LL, o += LL) {
        float4 e = *reinterpret_cast<const float4*>(p);
        float4 r;
        r.x = fexp(e.x - m.x) * is.x;
        r.y = fexp(e.y - m.y) * is.y;
        r.z = fexp(e.z - m.z) * is.z;
        r.w = fexp(e.w - m.w) * is.w;
        *reinterpret_cast<float4*>(o) = r;
    }
}

// ---------------------------------------------------------------------------
// Launch
// ---------------------------------------------------------------------------
extern "C" void kernel_launch(void* const* d_in, const int* in_sizes, int n_in,
                              void* d_out, int out_size)
{
    const float* x  = (const float*)d_in[0];
    const float* Wq = (const float*)d_in[1];
    const float* bq = (const float*)d_in[2];
    const float* Wk = (const float*)d_in[3];
    const float* bk = (const float*)d_in[4];
    const float* Wv = (const float*)d_in[5];
    const float* bv = (const float*)d_in[6];

    float* out  = (float*)d_out;
    float* Sp   = out;                                  // [B, 2L, D]
    float* Aout = out + (size_t)BB * 2 * LL * DD;       // [B, L, L]

    float *gV, *gE;
    __nv_bfloat16 *gQh, *gQl, *gKh, *gKl, *gVTh, *gVTl;
    cudaGetSymbolAddress((void**)&gV,  g_V);
    cudaGetSymbolAddress((void**)&gE,  g_E);
    cudaGetSymbolAddress((void**)&gQh, g_Qh);
    cudaGetSymbolAddress((void**)&gQl, g_Ql);
    cudaGetSymbolAddress((void**)&gKh, g_Kh);
    cudaGetSymbolAddress((void**)&gKl, g_Kl);
    cudaGetSymbolAddress((void**)&gVTh, g_VTh);
    cudaGetSymbolAddress((void**)&gVTl, g_VTl);

    const size_t sX  = (size_t)LL * DD;
    const size_t sSp = (size_t)2 * LL * DD;
    const size_t sE  = (size_t)LL * LL;

    // 1) QKV: Q -> Sp fp32 + hi/lo, K -> hi/lo, V -> fp32 scratch
    qkv_kernel<<<dim3(DD / BN, LL / BM, 3 * BB), 256>>>(
        x, Wq, bq, Wk, bk, Wv, bv, Sp, gV);

    // 2) V -> VT hi/lo
    vtrans_kernel<<<dim3(LL / 32, DD / 32, BB), 256>>>(gV);

    // 3) E = Q K^T / 16 with fused per-tile softmax partials
    mm_mma<false, true><<<dim3(LL / 128, LL / 128, BB), 256>>>(
        gQh, gQl, nullptr, DD, sX, gKh, gKl, DD, sX,
        gE, LL, sE, DD, 1.0f / 16.0f);

    // 4) softmax finalize over q
    softmax_combine<<<dim3(LL / 256, BB), 256>>>();
    softmax_write<<<dim3(LL / 1024, 32, BB), 256>>>(gE, Aout);

    // 5) C = A V -> Sp second half (A read as fp32, split during staging)
    mm_mma<true, false><<<dim3(DD / 128, LL / 128, BB), 256>>>(
        nullptr, nullptr, Aout, LL, sE, gVTh, gVTl, LL, (size_t)DD * LL,
        Sp + (size_t)LL * DD, DD, sSp, LL, 1.0f);

    (void)in_sizes; (void)n_in; (void)out_size;
}

// round 6
// speedup vs baseline: 2.9890x; 1.1650x over previous
#include <cuda_runtime.h>
#include <cuda_bf16.h>
#include <cstdint>
#include <cstddef>

// Problem constants
#define BB 8
#define LL 2048
#define DD 256

// ---------------------------------------------------------------------------
// Scratch (__device__ globals; no allocation allowed)
// ---------------------------------------------------------------------------
__device__ float          g_V [(size_t)BB * LL * DD];      // V fp32 (transpose src)
__device__ float          g_E [(size_t)BB * LL * LL];      // E fp32
__device__ __nv_bfloat16  g_xh[(size_t)BB * LL * DD];      // x hi/lo
__device__ __nv_bfloat16  g_xl[(size_t)BB * LL * DD];
__device__ __nv_bfloat16  g_Wh[3][DD * DD];                // Wq,Wk,Wv hi/lo
__device__ __nv_bfloat16  g_Wl[3][DD * DD];
__device__ __nv_bfloat16  g_Qh[(size_t)BB * LL * DD];
__device__ __nv_bfloat16  g_Ql[(size_t)BB * LL * DD];
__device__ __nv_bfloat16  g_Kh[(size_t)BB * LL * DD];
__device__ __nv_bfloat16  g_Kl[(size_t)BB * LL * DD];
__device__ __nv_bfloat16  g_VTh[(size_t)BB * DD * LL];     // V^T hi  [b][d][l]
__device__ __nv_bfloat16  g_VTl[(size_t)BB * DD * LL];
__device__ float g_pm[BB][16][LL];
__device__ float g_ps[BB][16][LL];
__device__ float g_m [BB][LL];
__device__ float g_is[BB][LL];

// ---------------------------------------------------------------------------
// Helpers
// ---------------------------------------------------------------------------
__device__ __forceinline__ uint32_t smem_u32(const void* p) {
    uint32_t a;
    asm("{ .reg .u64 t; cvta.to.shared.u64 t, %1; cvt.u32.u64 %0, t; }"
        : "=r"(a) : "l"(p));
    return a;
}

#define LDSM4(r, addr)                                                        \
    asm volatile("ldmatrix.sync.aligned.m8n8.x4.shared.b16 {%0,%1,%2,%3}, [%4];" \
                 : "=r"((r)[0]), "=r"((r)[1]), "=r"((r)[2]), "=r"((r)[3])     \
                 : "r"(addr))

#define MMA16816(d, a, b0, b1)                                                \
    asm volatile("mma.sync.aligned.m16n8k16.row.col.f32.bf16.bf16.f32 "       \
                 "{%0,%1,%2,%3}, {%4,%5,%6,%7}, {%8,%9}, {%0,%1,%2,%3};"      \
                 : "+f"((d)[0]), "+f"((d)[1]), "+f"((d)[2]), "+f"((d)[3])     \
                 : "r"((a)[0]), "r"((a)[1]), "r"((a)[2]), "r"((a)[3]),        \
                   "r"(b0), "r"(b1))

// Fast exp on the fma pipe (no MUFU); rel err ~2.4e-6
__device__ __forceinline__ float fexp(float x)
{
    x = fmaxf(x, -87.0f);
    float y = x * 1.4426950408889634f;
    float t = y + 12582912.0f;
    int   i = __float_as_int(t) - 0x4B400000;
    float f = y - (t - 12582912.0f);
    float p = 1.3333558146e-3f;
    p = fmaf(p, f, 9.6181291076e-3f);
    p = fmaf(p, f, 5.5504108664e-2f);
    p = fmaf(p, f, 2.4022650696e-1f);
    p = fmaf(p, f, 6.9314718056e-1f);
    p = fmaf(p, f, 1.0f);
    return __int_as_float(__float_as_int(p) + (i << 23));
}

__device__ __forceinline__ void bf16split4(const float* v, uint32_t& hi2, uint32_t& hi2b,
                                           uint32_t& lo2, uint32_t& lo2b)
{
    __nv_bfloat16 h[4], l[4];
#pragma unroll
    for (int j = 0; j < 4; j++) {
        h[j] = __float2bfloat16(v[j]);
        l[j] = __float2bfloat16(v[j] - __bfloat162float(h[j]));
    }
    hi2  = (uint32_t)*(uint16_t*)&h[0] | ((uint32_t)*(uint16_t*)&h[1] << 16);
    hi2b = (uint32_t)*(uint16_t*)&h[2] | ((uint32_t)*(uint16_t*)&h[3] << 16);
    lo2  = (uint32_t)*(uint16_t*)&l[0] | ((uint32_t)*(uint16_t*)&l[1] << 16);
    lo2b = (uint32_t)*(uint16_t*)&l[2] | ((uint32_t)*(uint16_t*)&l[3] << 16);
}

__device__ __forceinline__ uint32_t bf16pack2(float a, float b)
{
    __nv_bfloat16 ha = __float2bfloat16(a), hb = __float2bfloat16(b);
    return (uint32_t)*(uint16_t*)&ha | ((uint32_t)*(uint16_t*)&hb << 16);
}

// ---------------------------------------------------------------------------
// fp32 -> bf16 hi/lo split (elementwise, float4)
// ---------------------------------------------------------------------------
__global__ __launch_bounds__(256)
void split_kernel(const float* __restrict__ src, __nv_bfloat16* __restrict__ h,
                  __nv_bfloat16* __restrict__ l)
{
    const size_t i = ((size_t)blockIdx.x * 256 + threadIdx.x) * 4;
    float4 v4 = *reinterpret_cast<const float4*>(src + i);
    float v[4] = {v4.x, v4.y, v4.z, v4.w};
    uint32_t h0, h1, l0, l1;
    bf16split4(v, h0, h1, l0, l1);
    *reinterpret_cast<uint2*>(h + i) = make_uint2(h0, h1);
    *reinterpret_cast<uint2*>(l + i) = make_uint2(l0, l1);
}

// ---------------------------------------------------------------------------
// Common MMA compute macro pieces are repeated in 3 kernels:
//   mm_e   : E = Q K^T * scale, fused softmax partials
//   mm_av  : C = softmax-normalized(E) @ V^T, also writes A (n-tile 0)
//   mm_qkv : {Q,K,V} = x W^T + b, writes per-type outputs
// All: CTA tile 128x128, BK=32, 256 threads (8 warps 64x32), PITCH=80 smem.
// ---------------------------------------------------------------------------
#define PITCH 80

// stage a 128x32 bf16 tile pair (hi/lo) from gmem rows
#define STAGE_BF16(dsth, dstl, srch, srcl, ld, kc)                            \
    _Pragma("unroll")                                                         \
    for (int t = 0; t < 2; t++) {                                             \
        const int q = tid + t * 256;                                          \
        const int row = q >> 2, seg = q & 3;                                  \
        const uint32_t so = row * PITCH + seg * 16;                           \
        const size_t go = (size_t)row * (ld) + (size_t)(kc) * 32 + seg * 8;   \
        *reinterpret_cast<uint4*>((dsth) + so) =                              \
            *reinterpret_cast<const uint4*>((srch) + go);                     \
        *reinterpret_cast<uint4*>((dstl) + so) =                              \
            *reinterpret_cast<const uint4*>((srcl) + go);                     \
    }

// inner K=32 compute on staged tiles (3 MMA terms)
#define COMPUTE_CHUNK()                                                       \
    _Pragma("unroll")                                                         \
    for (int kk = 0; kk < 2; kk++) {                                          \
        uint32_t bhf[2][4], blf[2][4];                                        \
        LDSM4(bhf[0], bBaseH + kk * 32);                                      \
        LDSM4(bhf[1], bBaseH + 16 * PITCH + kk * 32);                         \
        LDSM4(blf[0], bBaseL + kk * 32);                                      \
        LDSM4(blf[1], bBaseL + 16 * PITCH + kk * 32);                         \
        _Pragma("unroll")                                                     \
        for (int mt = 0; mt < 4; mt++) {                                      \
            uint32_t ah[4], al[4];                                            \
            LDSM4(ah, aBaseH + mt * 16 * PITCH + kk * 32);                    \
            LDSM4(al, aBaseL + mt * 16 * PITCH + kk * 32);                    \
            _Pragma("unroll")                                                 \
            for (int g = 0; g < 2; g++) {                                     \
                _Pragma("unroll")                                             \
                for (int h = 0; h < 2; h++) {                                 \
                    float* acc = d[mt * 4 + g * 2 + h];                       \
                    MMA16816(acc, ah, bhf[g][h], bhf[g][h + 2]);              \
                    MMA16816(acc, ah, blf[g][h], blf[g][h + 2]);              \
                    MMA16816(acc, al, bhf[g][h], bhf[g][h + 2]);              \
                }                                                             \
            }                                                                 \
        }                                                                     \
    }

#define MM_PROLOGUE()                                                         \
    __shared__ __align__(16) uint8_t sAh[128 * PITCH];                        \
    __shared__ __align__(16) uint8_t sAl[128 * PITCH];                        \
    __shared__ __align__(16) uint8_t sBh[128 * PITCH];                        \
    __shared__ __align__(16) uint8_t sBl[128 * PITCH];                        \
    const int tid = threadIdx.x;                                              \
    const int lane = tid & 31;                                                \
    const int wm = (tid >> 5) & 1;                                            \
    const int wn = tid >> 6;                                                  \
    const uint32_t lrow = lane & 15, lhalf = lane >> 4;                       \
    const uint32_t aBaseH = smem_u32(sAh) + (wm * 64 + lrow) * PITCH + lhalf * 16; \
    const uint32_t aBaseL = smem_u32(sAl) + (wm * 64 + lrow) * PITCH + lhalf * 16; \
    const uint32_t bBaseH = smem_u32(sBh) + (wn * 32 + lrow) * PITCH + lhalf * 16; \
    const uint32_t bBaseL = smem_u32(sBl) + (wn * 32 + lrow) * PITCH + lhalf * 16; \
    float d[16][4];                                                           \
    _Pragma("unroll")                                                         \
    for (int i = 0; i < 16; i++)                                              \
        _Pragma("unroll")                                                     \
        for (int j = 0; j < 4; j++) d[i][j] = 0.0f;

// ---------------------------------------------------------------------------
// E = Q K^T / 16 with fused per-tile column softmax partials
// ---------------------------------------------------------------------------
__global__ __launch_bounds__(256, 2)
void mm_e(float* __restrict__ Ef)
{
    MM_PROLOGUE();
    const int b = blockIdx.z;
    const int n0 = blockIdx.x * 128, m0 = blockIdx.y * 128;

    const __nv_bfloat16* pAh = g_Qh + (size_t)b * LL * DD + (size_t)m0 * DD;
    const __nv_bfloat16* pAl = g_Ql + (size_t)b * LL * DD + (size_t)m0 * DD;
    const __nv_bfloat16* pBh = g_Kh + (size_t)b * LL * DD + (size_t)n0 * DD;
    const __nv_bfloat16* pBl = g_Kl + (size_t)b * LL * DD + (size_t)n0 * DD;

    for (int kc = 0; kc < DD / 32; kc++) {
        __syncthreads();
        STAGE_BF16(sAh, sAl, pAh, pAl, DD, kc);
        STAGE_BF16(sBh, sBl, pBh, pBl, DD, kc);
        __syncthreads();
        COMPUTE_CHUNK();
    }

#pragma unroll
    for (int i = 0; i < 16; i++)
#pragma unroll
        for (int j = 0; j < 4; j++) d[i][j] *= (1.0f / 16.0f);

    float* Cb = Ef + (size_t)b * LL * LL;
#pragma unroll
    for (int mt = 0; mt < 4; mt++) {
#pragma unroll
        for (int ni = 0; ni < 4; ni++) {
            const float* acc = d[mt * 4 + ni];
            const int row = m0 + wm * 64 + mt * 16 + (lane >> 2);
            const int col = n0 + wn * 32 + ni * 8 + (lane & 3) * 2;
            *reinterpret_cast<float2*>(&Cb[(size_t)row * LL + col]) =
                make_float2(acc[0], acc[1]);
            *reinterpret_cast<float2*>(&Cb[(size_t)(row + 8) * LL + col]) =
                make_float2(acc[2], acc[3]);
        }
    }

    // fused per-tile column softmax partials
    __shared__ float sMx[2][128];
    __shared__ float sSm[2][128];
#pragma unroll
    for (int ni = 0; ni < 4; ni++) {
#pragma unroll
        for (int p = 0; p < 2; p++) {
            float mx = -1e30f;
#pragma unroll
            for (int mt = 0; mt < 4; mt++)
                mx = fmaxf(mx, fmaxf(d[mt * 4 + ni][p], d[mt * 4 + ni][p + 2]));
            float sm = 0.0f;
#pragma unroll
            for (int mt = 0; mt < 4; mt++)
                sm += fexp(d[mt * 4 + ni][p] - mx) + fexp(d[mt * 4 + ni][p + 2] - mx);
#pragma unroll
            for (int off = 4; off < 32; off <<= 1) {
                float omx = __shfl_xor_sync(0xFFFFFFFFu, mx, off);
                float osm = __shfl_xor_sync(0xFFFFFFFFu, sm, off);
                float nm = fmaxf(mx, omx);
                sm = sm * fexp(mx - nm) + osm * fexp(omx - nm);
                mx = nm;
            }
            if ((lane >> 2) == 0) {
                const int c = wn * 32 + ni * 8 + (lane & 3) * 2 + p;
                sMx[wm][c] = mx;
                sSm[wm][c] = sm;
            }
        }
    }
    __syncthreads();
    if (tid < 128) {
        float m0v = sMx[0][tid], m1v = sMx[1][tid];
        float nm = fmaxf(m0v, m1v);
        float s = sSm[0][tid] * fexp(m0v - nm) + sSm[1][tid] * fexp(m1v - nm);
        g_pm[b][blockIdx.y][n0 + tid] = nm;
        g_ps[b][blockIdx.y][n0 + tid] = s;
    }
}

// ---------------------------------------------------------------------------
// C = A V^T' : stages A = exp(E - m[k]) * is[k] on the fly; n-tile 0 also
// writes A fp32 to Aout (the softmax output). B = V^T hi/lo.
// ---------------------------------------------------------------------------
__global__ __launch_bounds__(256, 2)
void mm_av(const float* __restrict__ Ef, float* __restrict__ Aout,
           float* __restrict__ Cout)
{
    MM_PROLOGUE();
    const int b = blockIdx.z;
    const int n0 = blockIdx.x * 128, m0 = blockIdx.y * 128;
    const bool writeA = (blockIdx.x == 0);

    const float*         pE  = Ef + (size_t)b * LL * LL + (size_t)m0 * LL;
    float*               pA  = Aout + (size_t)b * LL * LL + (size_t)m0 * LL;
    const __nv_bfloat16* pBh = g_VTh + (size_t)b * DD * LL + (size_t)n0 * LL;
    const __nv_bfloat16* pBl = g_VTl + (size_t)b * DD * LL + (size_t)n0 * LL;

    for (int kc = 0; kc < LL / 32; kc++) {
        __syncthreads();
        // stage A from E with softmax normalization
#pragma unroll
        for (int t = 0; t < 4; t++) {
            const int q = tid + t * 256;          // 0..1023
            const int row = q >> 3, seg = q & 7;
            const int k = kc * 32 + seg * 4;
            float4 e4 = *reinterpret_cast<const float4*>(pE + (size_t)row * LL + k);
            float4 m4 = *reinterpret_cast<const float4*>(&g_m[b][k]);
            float4 i4 = *reinterpret_cast<const float4*>(&g_is[b][k]);
            float v[4];
            v[0] = fexp(e4.x - m4.x) * i4.x;
            v[1] = fexp(e4.y - m4.y) * i4.y;
            v[2] = fexp(e4.z - m4.z) * i4.z;
            v[3] = fexp(e4.w - m4.w) * i4.w;
            if (writeA)
                *reinterpret_cast<float4*>(pA + (size_t)row * LL + k) =
                    make_float4(v[0], v[1], v[2], v[3]);
            uint32_t h0, h1, l0, l1;
            bf16split4(v, h0, h1, l0, l1);
            const uint32_t so = row * PITCH + seg * 8;
            *reinterpret_cast<uint2*>(sAh + so) = make_uint2(h0, h1);
            *reinterpret_cast<uint2*>(sAl + so) = make_uint2(l0, l1);
        }
        STAGE_BF16(sBh, sBl, pBh, pBl, LL, kc);
        __syncthreads();
        COMPUTE_CHUNK();
    }

    float* Cb = Cout + (size_t)b * 2 * LL * DD;   // Sp second half passed via Cout
#pragma unroll
    for (int mt = 0; mt < 4; mt++) {
#pragma unroll
        for (int ni = 0; ni < 4; ni++) {
            const float* acc = d[mt * 4 + ni];
            const int row = m0 + wm * 64 + mt * 16 + (lane >> 2);
            const int col = n0 + wn * 32 + ni * 8 + (lane & 3) * 2;
            *reinterpret_cast<float2*>(&Cb[(size_t)row * DD + col]) =
                make_float2(acc[0], acc[1]);
            *reinterpret_cast<float2*>(&Cb[(size_t)(row + 8) * DD + col]) =
                make_float2(acc[2], acc[3]);
        }
    }
}

// ---------------------------------------------------------------------------
// QKV: {Q,K,V}[r, n] = x[r, :] . W[n, :] + b[n], r over BB*LL folded rows.
// grid (2, 128, 3); z selects weight. Outputs per type.
// ---------------------------------------------------------------------------
__global__ __launch_bounds__(256, 2)
void mm_qkv(const float* __restrict__ bq, const float* __restrict__ bk,
            const float* __restrict__ bv, float* __restrict__ Sp)
{
    MM_PROLOGUE();
    const int w = blockIdx.z;
    const int n0 = blockIdx.x * 128, m0 = blockIdx.y * 128;

    const __nv_bfloat16* pAh = g_xh + (size_t)m0 * DD;
    const __nv_bfloat16* pAl = g_xl + (size_t)m0 * DD;
    const __nv_bfloat16* pBh = g_Wh[w] + (size_t)n0 * DD;
    const __nv_bfloat16* pBl = g_Wl[w] + (size_t)n0 * DD;

    for (int kc = 0; kc < DD / 32; kc++) {
        __syncthreads();
        STAGE_BF16(sAh, sAl, pAh, pAl, DD, kc);
        STAGE_BF16(sBh, sBl, pBh, pBl, DD, kc);
        __syncthreads();
        COMPUTE_CHUNK();
    }

    const float* bias = (w == 0) ? bq : (w == 1) ? bk : bv;

#pragma unroll
    for (int mt = 0; mt < 4; mt++) {
#pragma unroll
        for (int ni = 0; ni < 4; ni++) {
            float* acc = d[mt * 4 + ni];
            const int row = m0 + wm * 64 + mt * 16 + (lane >> 2);
            const int col = n0 + wn * 32 + ni * 8 + (lane & 3) * 2;
            const float b0 = bias[col], b1 = bias[col + 1];
            float v0 = acc[0] + b0, v1 = acc[1] + b1;
            float v2 = acc[2] + b0, v3 = acc[3] + b1;
            // row -> (batch, l)
            const int bb0 = row >> 11, l0i = row & 2047;
            const int bb1 = (row + 8) >> 11, l1i = (row + 8) & 2047;
            if (w == 0) {
                // Q: Sp fp32 + hi/lo bf16
                float* q0 = Sp + (size_t)bb0 * 2 * LL * DD + (size_t)l0i * DD + col;
                float* q1 = Sp + (size_t)bb1 * 2 * LL * DD + (size_t)l1i * DD + col;
                *reinterpret_cast<float2*>(q0) = make_float2(v0, v1);
                *reinterpret_cast<float2*>(q1) = make_float2(v2, v3);
                const size_t o0 = (size_t)row * DD + col;
                const size_t o1 = (size_t)(row + 8) * DD + col;
                __nv_bfloat16 h0 = __float2bfloat16(v0), h1 = __float2bfloat16(v1);
                __nv_bfloat16 h2 = __float2bfloat16(v2), h3 = __float2bfloat16(v3);
                *reinterpret_cast<uint32_t*>(&g_Qh[o0]) = bf16pack2(v0, v1);
                *reinterpret_cast<uint32_t*>(&g_Qh[o1]) = bf16pack2(v2, v3);
                *reinterpret_cast<uint32_t*>(&g_Ql[o0]) =
                    bf16pack2(v0 - __bfloat162float(h0), v1 - __bfloat162float(h1));
                *reinterpret_cast<uint32_t*>(&g_Ql[o1]) =
                    bf16pack2(v2 - __bfloat162float(h2), v3 - __bfloat162float(h3));
            } else if (w == 1) {
                const size_t o0 = (size_t)row * DD + col;
                const size_t o1 = (size_t)(row + 8) * DD + col;
                __nv_bfloat16 h0 = __float2bfloat16(v0), h1 = __float2bfloat16(v1);
                __nv_bfloat16 h2 = __float2bfloat16(v2), h3 = __float2bfloat16(v3);
                *reinterpret_cast<uint32_t*>(&g_Kh[o0]) = bf16pack2(v0, v1);
                *reinterpret_cast<uint32_t*>(&g_Kh[o1]) = bf16pack2(v2, v3);
                *reinterpret_cast<uint32_t*>(&g_Kl[o0]) =
                    bf16pack2(v0 - __bfloat162float(h0), v1 - __bfloat162float(h1));
                *reinterpret_cast<uint32_t*>(&g_Kl[o1]) =
                    bf16pack2(v2 - __bfloat162float(h2), v3 - __bfloat162float(h3));
            } else {
                float* p0 = g_V + (size_t)row * DD + col;
                float* p1 = g_V + (size_t)(row + 8) * DD + col;
                *reinterpret_cast<float2*>(p0) = make_float2(v0, v1);
                *reinterpret_cast<float2*>(p1) = make_float2(v2, v3);
            }
        }
    }
}

// ---------------------------------------------------------------------------
// V [b][l][d] fp32 -> VT hi/lo bf16 [b][d][l]
// ---------------------------------------------------------------------------
__global__ __launch_bounds__(256)
void vtrans_kernel(const float* __restrict__ V)
{
    __shared__ float t[32][33];
    const int b = blockIdx.z;
    const int l0 = blockIdx.x * 32, d0 = blockIdx.y * 32;
    const int tx = threadIdx.x & 31, ty = threadIdx.x >> 5;  // 32 x 8

    const float* Vb = V + (size_t)b * LL * DD;
#pragma unroll
    for (int i = 0; i < 4; i++)
        t[ty + i * 8][tx] = Vb[(size_t)(l0 + ty + i * 8) * DD + d0 + tx];
    __syncthreads();

    __nv_bfloat16* Th = g_VTh + (size_t)b * DD * LL;
    __nv_bfloat16* Tl = g_VTl + (size_t)b * DD * LL;
#pragma unroll
    for (int i = 0; i < 4; i++) {
        float v = t[tx][ty + i * 8];
        __nv_bfloat16 h = __float2bfloat16(v);
        __nv_bfloat16 l = __float2bfloat16(v - __bfloat162float(h));
        Th[(size_t)(d0 + ty + i * 8) * LL + l0 + tx] = h;
        Tl[(size_t)(d0 + ty + i * 8) * LL + l0 + tx] = l;
    }
}

// ---------------------------------------------------------------------------
// Softmax combine (16 partials per column)
// ---------------------------------------------------------------------------
__global__ __launch_bounds__(256)
void softmax_combine()
{
    const int b = blockIdx.y;
    const int col = blockIdx.x * 256 + threadIdx.x;
    float m = -1e30f;
#pragma unroll
    for (int c = 0; c < 16; c++) m = fmaxf(m, g_pm[b][c][col]);
    float s = 0.f;
#pragma unroll
    for (int c = 0; c < 16; c++) s += g_ps[b][c][col] * fexp(g_pm[b][c][col] - m);
    g_m[b][col] = m;
    g_is[b][col] = 1.0f / s;
}

// ---------------------------------------------------------------------------
// Launch
// ---------------------------------------------------------------------------
extern "C" void kernel_launch(void* const* d_in, const int* in_sizes, int n_in,
                              void* d_out, int out_size)
{
    const float* x  = (const float*)d_in[0];
    const float* Wq = (const float*)d_in[1];
    const float* bq = (const float*)d_in[2];
    const float* Wk = (const float*)d_in[3];
    const float* bk = (const float*)d_in[4];
    const float* Wv = (const float*)d_in[5];
    const float* bv = (const float*)d_in[6];

    float* out  = (float*)d_out;
    float* Sp   = out;                                  // [B, 2L, D]
    float* Aout = out + (size_t)BB * 2 * LL * DD;       // [B, L, L]

    float *gV, *gE;
    __nv_bfloat16 *gxh, *gxl, *gWh, *gWl;
    cudaGetSymbolAddress((void**)&gV,  g_V);
    cudaGetSymbolAddress((void**)&gE,  g_E);
    cudaGetSymbolAddress((void**)&gxh, g_xh);
    cudaGetSymbolAddress((void**)&gxl, g_xl);
    cudaGetSymbolAddress((void**)&gWh, g_Wh);
    cudaGetSymbolAddress((void**)&gWl, g_Wl);

    // 1) split x and W into bf16 hi/lo
    const size_t nx = (size_t)BB * LL * DD;     // 4,194,304
    split_kernel<<<(unsigned)(nx / 1024), 256>>>(x, gxh, gxl);
    split_kernel<<<DD * DD / 1024, 256>>>(Wq, gWh, gWl);
    split_kernel<<<DD * DD / 1024, 256>>>(Wk, gWh + DD * DD, gWl + DD * DD);
    split_kernel<<<DD * DD / 1024, 256>>>(Wv, gWh + 2 * DD * DD, gWl + 2 * DD * DD);

    // 2) QKV on tensor cores
    mm_qkv<<<dim3(2, (BB * LL) / 128, 3), 256>>>(bq, bk, bv, Sp);

    // 3) V -> VT hi/lo
    vtrans_kernel<<<dim3(LL / 32, DD / 32, BB), 256>>>(gV);

    // 4) E = Q K^T / 16 with fused softmax partials
    mm_e<<<dim3(LL / 128, LL / 128, BB), 256>>>(gE);

    // 5) softmax finalize
    softmax_combine<<<dim3(LL / 256, BB), 256>>>();

    // 6) C = A V (A computed from E on the fly; n-tile 0 writes A to d_out)
    mm_av<<<dim3(DD / 128, LL / 128, BB), 256>>>(gE, Aout, Sp + (size_t)LL * DD);

    (void)in_sizes; (void)n_in; (void)out_size;
}

// round 7
// speedup vs baseline: 3.0074x; 1.0062x over previous
#include <cuda_runtime.h>
#include <cuda_bf16.h>
#include <cstdint>
#include <cstddef>

// Problem constants
#define BB 8
#define LL 2048
#define DD 256

// ---------------------------------------------------------------------------
// Scratch (__device__ globals; no allocation allowed)
// ---------------------------------------------------------------------------
__device__ float          g_V [(size_t)BB * LL * DD];      // V fp32 (transpose src)
__device__ float          g_E [(size_t)BB * LL * LL];      // E fp32
__device__ __nv_bfloat16  g_xh[(size_t)BB * LL * DD];      // x hi/lo
__device__ __nv_bfloat16  g_xl[(size_t)BB * LL * DD];
__device__ __nv_bfloat16  g_Wh[3][DD * DD];                // Wq,Wk,Wv hi/lo
__device__ __nv_bfloat16  g_Wl[3][DD * DD];
__device__ __nv_bfloat16  g_Qh[(size_t)BB * LL * DD];
__device__ __nv_bfloat16  g_Ql[(size_t)BB * LL * DD];
__device__ __nv_bfloat16  g_Kh[(size_t)BB * LL * DD];
__device__ __nv_bfloat16  g_Kl[(size_t)BB * LL * DD];
__device__ __nv_bfloat16  g_VTh[(size_t)BB * DD * LL];     // V^T hi  [b][d][l]
__device__ __nv_bfloat16  g_VTl[(size_t)BB * DD * LL];
__device__ float g_pm[BB][16][LL];
__device__ float g_ps[BB][16][LL];
__device__ float g_m [BB][LL];
__device__ float g_is[BB][LL];

// ---------------------------------------------------------------------------
// Helpers
// ---------------------------------------------------------------------------
__device__ __forceinline__ uint32_t smem_u32(const void* p) {
    uint32_t a;
    asm("{ .reg .u64 t; cvta.to.shared.u64 t, %1; cvt.u32.u64 %0, t; }"
        : "=r"(a) : "l"(p));
    return a;
}

#define LDSM4(r, addr)                                                        \
    asm volatile("ldmatrix.sync.aligned.m8n8.x4.shared.b16 {%0,%1,%2,%3}, [%4];" \
                 : "=r"((r)[0]), "=r"((r)[1]), "=r"((r)[2]), "=r"((r)[3])     \
                 : "r"(addr))

#define MMA16816(d, a, b0, b1)                                                \
    asm volatile("mma.sync.aligned.m16n8k16.row.col.f32.bf16.bf16.f32 "       \
                 "{%0,%1,%2,%3}, {%4,%5,%6,%7}, {%8,%9}, {%0,%1,%2,%3};"      \
                 : "+f"((d)[0]), "+f"((d)[1]), "+f"((d)[2]), "+f"((d)[3])     \
                 : "r"((a)[0]), "r"((a)[1]), "r"((a)[2]), "r"((a)[3]),        \
                   "r"(b0), "r"(b1))

#define CP16(dst, src)                                                        \
    asm volatile("cp.async.cg.shared.global [%0], [%1], 16;"                  \
                 :: "r"(dst), "l"(src))
#define CP_COMMIT() asm volatile("cp.async.commit_group;" ::: "memory")
#define CP_WAIT1()  asm volatile("cp.async.wait_group 1;" ::: "memory")
#define CP_WAIT0()  asm volatile("cp.async.wait_group 0;" ::: "memory")

// Fast exp on the fma pipe (no MUFU); rel err ~2.4e-6
__device__ __forceinline__ float fexp(float x)
{
    x = fmaxf(x, -87.0f);
    float y = x * 1.4426950408889634f;
    float t = y + 12582912.0f;
    int   i = __float_as_int(t) - 0x4B400000;
    float f = y - (t - 12582912.0f);
    float p = 1.3333558146e-3f;
    p = fmaf(p, f, 9.6181291076e-3f);
    p = fmaf(p, f, 5.5504108664e-2f);
    p = fmaf(p, f, 2.4022650696e-1f);
    p = fmaf(p, f, 6.9314718056e-1f);
    p = fmaf(p, f, 1.0f);
    return __int_as_float(__float_as_int(p) + (i << 23));
}

__device__ __forceinline__ void bf16split4(const float* v, uint32_t& hi2, uint32_t& hi2b,
                                           uint32_t& lo2, uint32_t& lo2b)
{
    __nv_bfloat16 h[4], l[4];
#pragma unroll
    for (int j = 0; j < 4; j++) {
        h[j] = __float2bfloat16(v[j]);
        l[j] = __float2bfloat16(v[j] - __bfloat162float(h[j]));
    }
    hi2  = (uint32_t)*(uint16_t*)&h[0] | ((uint32_t)*(uint16_t*)&h[1] << 16);
    hi2b = (uint32_t)*(uint16_t*)&h[2] | ((uint32_t)*(uint16_t*)&h[3] << 16);
    lo2  = (uint32_t)*(uint16_t*)&l[0] | ((uint32_t)*(uint16_t*)&l[1] << 16);
    lo2b = (uint32_t)*(uint16_t*)&l[2] | ((uint32_t)*(uint16_t*)&l[3] << 16);
}

__device__ __forceinline__ uint32_t bf16pack2(float a, float b)
{
    __nv_bfloat16 ha = __float2bfloat16(a), hb = __float2bfloat16(b);
    return (uint32_t)*(uint16_t*)&ha | ((uint32_t)*(uint16_t*)&hb << 16);
}

// ---------------------------------------------------------------------------
// fp32 -> bf16 hi/lo split (elementwise, float4)
// ---------------------------------------------------------------------------
__global__ __launch_bounds__(256)
void split_kernel(const float* __restrict__ src, __nv_bfloat16* __restrict__ h,
                  __nv_bfloat16* __restrict__ l)
{
    const size_t i = ((size_t)blockIdx.x * 256 + threadIdx.x) * 4;
    float4 v4 = *reinterpret_cast<const float4*>(src + i);
    float v[4] = {v4.x, v4.y, v4.z, v4.w};
    uint32_t h0, h1, l0, l1;
    bf16split4(v, h0, h1, l0, l1);
    *reinterpret_cast<uint2*>(h + i) = make_uint2(h0, h1);
    *reinterpret_cast<uint2*>(l + i) = make_uint2(l0, l1);
}

// ---------------------------------------------------------------------------
// MMA kernels: CTA tile 128x128, BK=32, 256 threads (8 warps 64x32).
// Dynamic smem: 2 buffers x [Ah|Al|Bh|Bl] of 128*PITCH each (PITCH=80).
// cp.async double-buffered pipeline.
// ---------------------------------------------------------------------------
#define PITCH 80
#define TILEB (128 * PITCH)            // 10240
#define BUFB  (4 * TILEB)              // 40960
#define MM_SMEM (2 * BUFB)             // 81920

// stage a 128x32 bf16 tile pair (hi/lo) via cp.async into smem u32 bases
#define CPSTAGE(dh, dl, srch, srcl, ld, kc)                                   \
    _Pragma("unroll")                                                         \
    for (int t = 0; t < 2; t++) {                                             \
        const int q = tid + t * 256;                                          \
        const int row = q >> 2, seg = q & 3;                                  \
        const uint32_t so = row * PITCH + seg * 16;                           \
        const size_t go = (size_t)row * (ld) + (size_t)(kc) * 32 + seg * 8;   \
        CP16((dh) + so, (srch) + go);                                         \
        CP16((dl) + so, (srcl) + go);                                         \
    }

// inner K=32 compute on staged tiles at given smem bases
#define COMPUTE_CHUNK(aH, aL, bH, bL)                                         \
    _Pragma("unroll")                                                         \
    for (int kk = 0; kk < 2; kk++) {                                          \
        uint32_t bhf[2][4], blf[2][4];                                        \
        LDSM4(bhf[0], (bH) + relB + kk * 32);                                 \
        LDSM4(bhf[1], (bH) + relB + 16 * PITCH + kk * 32);                    \
        LDSM4(blf[0], (bL) + relB + kk * 32);                                 \
        LDSM4(blf[1], (bL) + relB + 16 * PITCH + kk * 32);                    \
        _Pragma("unroll")                                                     \
        for (int mt = 0; mt < 4; mt++) {                                      \
            uint32_t ah[4], al[4];                                            \
            LDSM4(ah, (aH) + relA + mt * 16 * PITCH + kk * 32);               \
            LDSM4(al, (aL) + relA + mt * 16 * PITCH + kk * 32);               \
            _Pragma("unroll")                                                 \
            for (int g = 0; g < 2; g++) {                                     \
                _Pragma("unroll")                                             \
                for (int h = 0; h < 2; h++) {                                 \
                    float* acc = d[mt * 4 + g * 2 + h];                       \
                    MMA16816(acc, ah, bhf[g][h], bhf[g][h + 2]);              \
                    MMA16816(acc, ah, blf[g][h], blf[g][h + 2]);              \
                    MMA16816(acc, al, bhf[g][h], bhf[g][h + 2]);              \
                }                                                             \
            }                                                                 \
        }                                                                     \
    }

#define MM_PROLOGUE()                                                         \
    extern __shared__ __align__(16) uint8_t smem[];                           \
    const uint32_t sb = smem_u32(smem);                                       \
    const int tid = threadIdx.x;                                              \
    const int lane = tid & 31;                                                \
    const int wm = (tid >> 5) & 1;                                            \
    const int wn = tid >> 6;                                                  \
    const uint32_t lrow = lane & 15, lhalf = lane >> 4;                       \
    const uint32_t relA = (wm * 64 + lrow) * PITCH + lhalf * 16;              \
    const uint32_t relB = (wn * 32 + lrow) * PITCH + lhalf * 16;              \
    float d[16][4];                                                           \
    _Pragma("unroll")                                                         \
    for (int i = 0; i < 16; i++)                                              \
        _Pragma("unroll")                                                     \
        for (int j = 0; j < 4; j++) d[i][j] = 0.0f;

// buffer base addresses
#define BUF_AH(bi) (sb + (bi) * BUFB)
#define BUF_AL(bi) (sb + (bi) * BUFB + TILEB)
#define BUF_BH(bi) (sb + (bi) * BUFB + 2 * TILEB)
#define BUF_BL(bi) (sb + (bi) * BUFB + 3 * TILEB)

// ---------------------------------------------------------------------------
// E = Q K^T / 16 with fused per-tile column softmax partials
// ---------------------------------------------------------------------------
__global__ __launch_bounds__(256, 2)
void mm_e(float* __restrict__ Ef)
{
    MM_PROLOGUE();
    const int b = blockIdx.z;
    const int n0 = blockIdx.x * 128, m0 = blockIdx.y * 128;

    const __nv_bfloat16* pAh = g_Qh + (size_t)b * LL * DD + (size_t)m0 * DD;
    const __nv_bfloat16* pAl = g_Ql + (size_t)b * LL * DD + (size_t)m0 * DD;
    const __nv_bfloat16* pBh = g_Kh + (size_t)b * LL * DD + (size_t)n0 * DD;
    const __nv_bfloat16* pBl = g_Kl + (size_t)b * LL * DD + (size_t)n0 * DD;

    const int NCH = DD / 32;   // 8
    // prologue: prefetch chunks 0, 1
    CPSTAGE(BUF_AH(0), BUF_AL(0), pAh, pAl, DD, 0);
    CPSTAGE(BUF_BH(0), BUF_BL(0), pBh, pBl, DD, 0);
    CP_COMMIT();
    CPSTAGE(BUF_AH(1), BUF_AL(1), pAh, pAl, DD, 1);
    CPSTAGE(BUF_BH(1), BUF_BL(1), pBh, pBl, DD, 1);
    CP_COMMIT();

    for (int kc = 0; kc < NCH; kc++) {
        const int bi = kc & 1;
        if (kc == NCH - 1) { CP_WAIT0(); } else { CP_WAIT1(); }
        __syncthreads();
        COMPUTE_CHUNK(BUF_AH(bi), BUF_AL(bi), BUF_BH(bi), BUF_BL(bi));
        __syncthreads();
        if (kc + 2 < NCH) {
            CPSTAGE(BUF_AH(bi), BUF_AL(bi), pAh, pAl, DD, kc + 2);
            CPSTAGE(BUF_BH(bi), BUF_BL(bi), pBh, pBl, DD, kc + 2);
            CP_COMMIT();
        }
    }

#pragma unroll
    for (int i = 0; i < 16; i++)
#pragma unroll
        for (int j = 0; j < 4; j++) d[i][j] *= (1.0f / 16.0f);

    float* Cb = Ef + (size_t)b * LL * LL;
#pragma unroll
    for (int mt = 0; mt < 4; mt++) {
#pragma unroll
        for (int ni = 0; ni < 4; ni++) {
            const float* acc = d[mt * 4 + ni];
            const int row = m0 + wm * 64 + mt * 16 + (lane >> 2);
            const int col = n0 + wn * 32 + ni * 8 + (lane & 3) * 2;
            *reinterpret_cast<float2*>(&Cb[(size_t)row * LL + col]) =
                make_float2(acc[0], acc[1]);
            *reinterpret_cast<float2*>(&Cb[(size_t)(row + 8) * LL + col]) =
                make_float2(acc[2], acc[3]);
        }
    }

    // fused per-tile column softmax partials (reuse smem buffers)
    float* sMx = reinterpret_cast<float*>(smem);          // [2][128]
    float* sSm = reinterpret_cast<float*>(smem) + 256;    // [2][128]
    __syncthreads();
#pragma unroll
    for (int ni = 0; ni < 4; ni++) {
#pragma unroll
        for (int p = 0; p < 2; p++) {
            float mx = -1e30f;
#pragma unroll
            for (int mt = 0; mt < 4; mt++)
                mx = fmaxf(mx, fmaxf(d[mt * 4 + ni][p], d[mt * 4 + ni][p + 2]));
            float sm = 0.0f;
#pragma unroll
            for (int mt = 0; mt < 4; mt++)
                sm += fexp(d[mt * 4 + ni][p] - mx) + fexp(d[mt * 4 + ni][p + 2] - mx);
#pragma unroll
            for (int off = 4; off < 32; off <<= 1) {
                float omx = __shfl_xor_sync(0xFFFFFFFFu, mx, off);
                float osm = __shfl_xor_sync(0xFFFFFFFFu, sm, off);
                float nm = fmaxf(mx, omx);
                sm = sm * fexp(mx - nm) + osm * fexp(omx - nm);
                mx = nm;
            }
            if ((lane >> 2) == 0) {
                const int c = wn * 32 + ni * 8 + (lane & 3) * 2 + p;
                sMx[wm * 128 + c] = mx;
                sSm[wm * 128 + c] = sm;
            }
        }
    }
    __syncthreads();
    if (tid < 128) {
        float m0v = sMx[tid], m1v = sMx[128 + tid];
        float nm = fmaxf(m0v, m1v);
        float s = sSm[tid] * fexp(m0v - nm) + sSm[128 + tid] * fexp(m1v - nm);
        g_pm[b][blockIdx.y][n0 + tid] = nm;
        g_ps[b][blockIdx.y][n0 + tid] = s;
    }
}

// ---------------------------------------------------------------------------
// C = A V^T' : stages A = exp(E - m[k]) * is[k] on the fly (register-
// prefetched E); n-tile x writes A fp32 for k-chunks [x*32, x*32+32).
// ---------------------------------------------------------------------------
__global__ __launch_bounds__(256, 2)
void mm_av(const float* __restrict__ Ef, float* __restrict__ Aout,
           float* __restrict__ Cout)
{
    MM_PROLOGUE();
    const int b = blockIdx.z;
    const int n0 = blockIdx.x * 128, m0 = blockIdx.y * 128;

    const float*         pE  = Ef + (size_t)b * LL * LL + (size_t)m0 * LL;
    float*               pA  = Aout + (size_t)b * LL * LL + (size_t)m0 * LL;
    const __nv_bfloat16* pBh = g_VTh + (size_t)b * DD * LL + (size_t)n0 * LL;
    const __nv_bfloat16* pBl = g_VTl + (size_t)b * DD * LL + (size_t)n0 * LL;

    const int NCH = LL / 32;   // 64
    const int wlo = blockIdx.x * 32, whi = wlo + 32;   // A-write chunk range

    // prologue: E regs for chunk 0; cp.async B chunks 0,1
    float4 e4[4];
    const int prow = tid >> 3, pseg = tid & 7;   // thread's 4 float4s: rows prow, prow+32.. no: 4 per thread
    // each thread owns 4 consecutive (row-groups): rows (tid>>3) + t*32? Use same layout as staging loop:
    // q = tid + t*256 -> row = q>>3, seg = q&7
#pragma unroll
    for (int t = 0; t < 4; t++) {
        const int q = tid + t * 256;
        const int row = q >> 3, seg = q & 7;
        e4[t] = *reinterpret_cast<const float4*>(pE + (size_t)row * LL + 0 * 32 + seg * 4);
    }
    CPSTAGE(BUF_BH(0), BUF_BL(0), pBh, pBl, LL, 0);
    CP_COMMIT();
    CPSTAGE(BUF_BH(1), BUF_BL(1), pBh, pBl, LL, 1);
    CP_COMMIT();

    for (int kc = 0; kc < NCH; kc++) {
        const int bi = kc & 1;
        const bool wA = (kc >= wlo) && (kc < whi);
        // transform prefetched E regs -> A smem (and optional A write)
#pragma unroll
        for (int t = 0; t < 4; t++) {
            const int q = tid + t * 256;
            const int row = q >> 3, seg = q & 7;
            const int k = kc * 32 + seg * 4;
            float4 m4 = *reinterpret_cast<const float4*>(&g_m[b][k]);
            float4 i4 = *reinterpret_cast<const float4*>(&g_is[b][k]);
            float v[4];
            v[0] = fexp(e4[t].x - m4.x) * i4.x;
            v[1] = fexp(e4[t].y - m4.y) * i4.y;
            v[2] = fexp(e4[t].z - m4.z) * i4.z;
            v[3] = fexp(e4[t].w - m4.w) * i4.w;
            if (wA)
                *reinterpret_cast<float4*>(pA + (size_t)row * LL + k) =
                    make_float4(v[0], v[1], v[2], v[3]);
            uint32_t h0, h1, l0, l1;
            bf16split4(v, h0, h1, l0, l1);
            const uint32_t so = row * PITCH + seg * 8;
            *reinterpret_cast<uint2*>(smem + bi * BUFB + so) = make_uint2(h0, h1);
            *reinterpret_cast<uint2*>(smem + bi * BUFB + TILEB + so) = make_uint2(l0, l1);
        }
        if (kc == NCH - 1) { CP_WAIT0(); } else { CP_WAIT1(); }
        __syncthreads();
        // prefetch next chunk's E into regs (overlaps compute)
        if (kc + 1 < NCH) {
#pragma unroll
            for (int t = 0; t < 4; t++) {
                const int q = tid + t * 256;
                const int row = q >> 3, seg = q & 7;
                e4[t] = *reinterpret_cast<const float4*>(
                    pE + (size_t)row * LL + (size_t)(kc + 1) * 32 + seg * 4);
            }
        }
        COMPUTE_CHUNK(BUF_AH(bi), BUF_AL(bi), BUF_BH(bi), BUF_BL(bi));
        __syncthreads();
        if (kc + 2 < NCH) {
            CPSTAGE(BUF_BH(bi), BUF_BL(bi), pBh, pBl, LL, kc + 2);
            CP_COMMIT();
        }
    }

    float* Cb = Cout + (size_t)b * 2 * LL * DD;   // Sp second half passed via Cout
#pragma unroll
    for (int mt = 0; mt < 4; mt++) {
#pragma unroll
        for (int ni = 0; ni < 4; ni++) {
            const float* acc = d[mt * 4 + ni];
            const int row = m0 + wm * 64 + mt * 16 + (lane >> 2);
            const int col = n0 + wn * 32 + ni * 8 + (lane & 3) * 2;
            *reinterpret_cast<float2*>(&Cb[(size_t)row * DD + col]) =
                make_float2(acc[0], acc[1]);
            *reinterpret_cast<float2*>(&Cb[(size_t)(row + 8) * DD + col]) =
                make_float2(acc[2], acc[3]);
        }
    }
    (void)prow; (void)pseg;
}

// ---------------------------------------------------------------------------
// QKV: {Q,K,V}[r, n] = x[r, :] . W[n, :] + b[n], r over BB*LL folded rows.
// ---------------------------------------------------------------------------
__global__ __launch_bounds__(256, 2)
void mm_qkv(const float* __restrict__ bq, const float* __restrict__ bk,
            const float* __restrict__ bv, float* __restrict__ Sp)
{
    MM_PROLOGUE();
    const int w = blockIdx.z;
    const int n0 = blockIdx.x * 128, m0 = blockIdx.y * 128;

    const __nv_bfloat16* pAh = g_xh + (size_t)m0 * DD;
    const __nv_bfloat16* pAl = g_xl + (size_t)m0 * DD;
    const __nv_bfloat16* pBh = g_Wh[w] + (size_t)n0 * DD;
    const __nv_bfloat16* pBl = g_Wl[w] + (size_t)n0 * DD;

    const int NCH = DD / 32;   // 8
    CPSTAGE(BUF_AH(0), BUF_AL(0), pAh, pAl, DD, 0);
    CPSTAGE(BUF_BH(0), BUF_BL(0), pBh, pBl, DD, 0);
    CP_COMMIT();
    CPSTAGE(BUF_AH(1), BUF_AL(1), pAh, pAl, DD, 1);
    CPSTAGE(BUF_BH(1), BUF_BL(1), pBh, pBl, DD, 1);
    CP_COMMIT();

    for (int kc = 0; kc < NCH; kc++) {
        const int bi = kc & 1;
        if (kc == NCH - 1) { CP_WAIT0(); } else { CP_WAIT1(); }
        __syncthreads();
        COMPUTE_CHUNK(BUF_AH(bi), BUF_AL(bi), BUF_BH(bi), BUF_BL(bi));
        __syncthreads();
        if (kc + 2 < NCH) {
            CPSTAGE(BUF_AH(bi), BUF_AL(bi), pAh, pAl, DD, kc + 2);
            CPSTAGE(BUF_BH(bi), BUF_BL(bi), pBh, pBl, DD, kc + 2);
            CP_COMMIT();
        }
    }

    const float* bias = (w == 0) ? bq : (w == 1) ? bk : bv;

#pragma unroll
    for (int mt = 0; mt < 4; mt++) {
#pragma unroll
        for (int ni = 0; ni < 4; ni++) {
            float* acc = d[mt * 4 + ni];
            const int row = m0 + wm * 64 + mt * 16 + (lane >> 2);
            const int col = n0 + wn * 32 + ni * 8 + (lane & 3) * 2;
            const float b0 = bias[col], b1 = bias[col + 1];
            float v0 = acc[0] + b0, v1 = acc[1] + b1;
            float v2 = acc[2] + b0, v3 = acc[3] + b1;
            const int bb0 = row >> 11, l0i = row & 2047;
            const int bb1 = (row + 8) >> 11, l1i = (row + 8) & 2047;
            if (w == 0) {
                float* q0 = Sp + (size_t)bb0 * 2 * LL * DD + (size_t)l0i * DD + col;
                float* q1 = Sp + (size_t)bb1 * 2 * LL * DD + (size_t)l1i * DD + col;
                *reinterpret_cast<float2*>(q0) = make_float2(v0, v1);
                *reinterpret_cast<float2*>(q1) = make_float2(v2, v3);
                const size_t o0 = (size_t)row * DD + col;
                const size_t o1 = (size_t)(row + 8) * DD + col;
                __nv_bfloat16 h0 = __float2bfloat16(v0), h1 = __float2bfloat16(v1);
                __nv_bfloat16 h2 = __float2bfloat16(v2), h3 = __float2bfloat16(v3);
                *reinterpret_cast<uint32_t*>(&g_Qh[o0]) = bf16pack2(v0, v1);
                *reinterpret_cast<uint32_t*>(&g_Qh[o1]) = bf16pack2(v2, v3);
                *reinterpret_cast<uint32_t*>(&g_Ql[o0]) =
                    bf16pack2(v0 - __bfloat162float(h0), v1 - __bfloat162float(h1));
                *reinterpret_cast<uint32_t*>(&g_Ql[o1]) =
                    bf16pack2(v2 - __bfloat162float(h2), v3 - __bfloat162float(h3));
            } else if (w == 1) {
                const size_t o0 = (size_t)row * DD + col;
                const size_t o1 = (size_t)(row + 8) * DD + col;
                __nv_bfloat16 h0 = __float2bfloat16(v0), h1 = __float2bfloat16(v1);
                __nv_bfloat16 h2 = __float2bfloat16(v2), h3 = __float2bfloat16(v3);
                *reinterpret_cast<uint32_t*>(&g_Kh[o0]) = bf16pack2(v0, v1);
                *reinterpret_cast<uint32_t*>(&g_Kh[o1]) = bf16pack2(v2, v3);
                *reinterpret_cast<uint32_t*>(&g_Kl[o0]) =
                    bf16pack2(v0 - __bfloat162float(h0), v1 - __bfloat162float(h1));
                *reinterpret_cast<uint32_t*>(&g_Kl[o1]) =
                    bf16pack2(v2 - __bfloat162float(h2), v3 - __bfloat162float(h3));
            } else {
                float* p0 = g_V + (size_t)row * DD + col;
                float* p1 = g_V + (size_t)(row + 8) * DD + col;
                *reinterpret_cast<float2*>(p0) = make_float2(v0, v1);
                *reinterpret_cast<float2*>(p1) = make_float2(v2, v3);
            }
        }
    }
}

// ---------------------------------------------------------------------------
// V [b][l][d] fp32 -> VT hi/lo bf16 [b][d][l]
// ---------------------------------------------------------------------------
__global__ __launch_bounds__(256)
void vtrans_kernel(const float* __restrict__ V)
{
    __shared__ float t[32][33];
    const int b = blockIdx.z;
    const int l0 = blockIdx.x * 32, d0 = blockIdx.y * 32;
    const int tx = threadIdx.x & 31, ty = threadIdx.x >> 5;  // 32 x 8

    const float* Vb = V + (size_t)b * LL * DD;
#pragma unroll
    for (int i = 0; i < 4; i++)
        t[ty + i * 8][tx] = Vb[(size_t)(l0 + ty + i * 8) * DD + d0 + tx];
    __syncthreads();

    __nv_bfloat16* Th = g_VTh + (size_t)b * DD * LL;
    __nv_bfloat16* Tl = g_VTl + (size_t)b * DD * LL;
#pragma unroll
    for (int i = 0; i < 4; i++) {
        float v = t[tx][ty + i * 8];
        __nv_bfloat16 h = __float2bfloat16(v);
        __nv_bfloat16 l = __float2bfloat16(v - __bfloat162float(h));
        Th[(size_t)(d0 + ty + i * 8) * LL + l0 + tx] = h;
        Tl[(size_t)(d0 + ty + i * 8) * LL + l0 + tx] = l;
    }
}

// ---------------------------------------------------------------------------
// Softmax combine (16 partials per column)
// ---------------------------------------------------------------------------
__global__ __launch_bounds__(256)
void softmax_combine()
{
    const int b = blockIdx.y;
    const int col = blockIdx.x * 256 + threadIdx.x;
    float m = -1e30f;
#pragma unroll
    for (int c = 0; c < 16; c++) m = fmaxf(m, g_pm[b][c][col]);
    float s = 0.f;
#pragma unroll
    for (int c = 0; c < 16; c++) s += g_ps[b][c][col] * fexp(g_pm[b][c][col] - m);
    g_m[b][col] = m;
    g_is[b][col] = 1.0f / s;
}

// ---------------------------------------------------------------------------
// Launch
// ---------------------------------------------------------------------------
extern "C" void kernel_launch(void* const* d_in, const int* in_sizes, int n_in,
                              void* d_out, int out_size)
{
    const float* x  = (const float*)d_in[0];
    const float* Wq = (const float*)d_in[1];
    const float* bq = (const float*)d_in[2];
    const float* Wk = (const float*)d_in[3];
    const float* bk = (const float*)d_in[4];
    const float* Wv = (const float*)d_in[5];
    const float* bv = (const float*)d_in[6];

    float* out  = (float*)d_out;
    float* Sp   = out;                                  // [B, 2L, D]
    float* Aout = out + (size_t)BB * 2 * LL * DD;       // [B, L, L]

    float *gV, *gE;
    __nv_bfloat16 *gxh, *gxl, *gWh, *gWl;
    cudaGetSymbolAddress((void**)&gV,  g_V);
    cudaGetSymbolAddress((void**)&gE,  g_E);
    cudaGetSymbolAddress((void**)&gxh, g_xh);
    cudaGetSymbolAddress((void**)&gxl, g_xl);
    cudaGetSymbolAddress((void**)&gWh, g_Wh);
    cudaGetSymbolAddress((void**)&gWl, g_Wl);

    cudaFuncSetAttribute(mm_e,   cudaFuncAttributeMaxDynamicSharedMemorySize, MM_SMEM);
    cudaFuncSetAttribute(mm_av,  cudaFuncAttributeMaxDynamicSharedMemorySize, MM_SMEM);
    cudaFuncSetAttribute(mm_qkv, cudaFuncAttributeMaxDynamicSharedMemorySize, MM_SMEM);

    // 1) split x and W into bf16 hi/lo
    const size_t nx = (size_t)BB * LL * DD;
    split_kernel<<<(unsigned)(nx / 1024), 256>>>(x, gxh, gxl);
    split_kernel<<<DD * DD / 1024, 256>>>(Wq, gWh, gWl);
    split_kernel<<<DD * DD / 1024, 256>>>(Wk, gWh + DD * DD, gWl + DD * DD);
    split_kernel<<<DD * DD / 1024, 256>>>(Wv, gWh + 2 * DD * DD, gWl + 2 * DD * DD);

    // 2) QKV on tensor cores
    mm_qkv<<<dim3(2, (BB * LL) / 128, 3), 256, MM_SMEM>>>(bq, bk, bv, Sp);

    // 3) V -> VT hi/lo
    vtrans_kernel<<<dim3(LL / 32, DD / 32, BB), 256>>>(gV);

    // 4) E = Q K^T / 16 with fused softmax partials
    mm_e<<<dim3(LL / 128, LL / 128, BB), 256, MM_SMEM>>>(gE);

    // 5) softmax finalize
    softmax_combine<<<dim3(LL / 256, BB), 256>>>();

    // 6) C = A V (A computed from E on the fly; n-tiles split the A writes)
    mm_av<<<dim3(DD / 128, LL / 128, BB), 256, MM_SMEM>>>(gE, Aout, Sp + (size_t)LL * DD);

    (void)in_sizes; (void)n_in; (void)out_size;
}

// round 8
// speedup vs baseline: 3.8662x; 1.2856x over previous
#include <cuda_runtime.h>
#include <cuda_bf16.h>
#include <cuda_fp16.h>
#include <cstdint>
#include <cstddef>

// Problem constants
#define BB 8
#define LL 2048
#define DD 256

// ---------------------------------------------------------------------------
// Scratch (__device__ globals; no allocation allowed)
// ---------------------------------------------------------------------------
__device__ float          g_V [(size_t)BB * LL * DD];      // V fp32 (transpose src)
__device__ float          g_E [(size_t)BB * LL * LL];      // E fp32
__device__ __nv_bfloat16  g_xh[(size_t)BB * LL * DD];      // x hi/lo (bf16, QKV 3-term)
__device__ __nv_bfloat16  g_xl[(size_t)BB * LL * DD];
__device__ __nv_bfloat16  g_Wh[3][DD * DD];
__device__ __nv_bfloat16  g_Wl[3][DD * DD];
__device__ __half         g_Qh[(size_t)BB * LL * DD];      // fp16 2-term operands
__device__ __half         g_Ql[(size_t)BB * LL * DD];
__device__ __half         g_Kh[(size_t)BB * LL * DD];      // K: hi only
__device__ __half         g_VTh[(size_t)BB * DD * LL];     // V^T: hi only [b][d][l]
__device__ float g_pm[BB][16][LL];
__device__ float g_ps[BB][16][LL];
__device__ float g_m [BB][LL];
__device__ float g_is[BB][LL];

// ---------------------------------------------------------------------------
// Helpers
// ---------------------------------------------------------------------------
__device__ __forceinline__ uint32_t smem_u32(const void* p) {
    uint32_t a;
    asm("{ .reg .u64 t; cvta.to.shared.u64 t, %1; cvt.u32.u64 %0, t; }"
        : "=r"(a) : "l"(p));
    return a;
}

#define LDSM4(r, addr)                                                        \
    asm volatile("ldmatrix.sync.aligned.m8n8.x4.shared.b16 {%0,%1,%2,%3}, [%4];" \
                 : "=r"((r)[0]), "=r"((r)[1]), "=r"((r)[2]), "=r"((r)[3])     \
                 : "r"(addr))

#define MMA_BF16(d, a, b0, b1)                                                \
    asm volatile("mma.sync.aligned.m16n8k16.row.col.f32.bf16.bf16.f32 "       \
                 "{%0,%1,%2,%3}, {%4,%5,%6,%7}, {%8,%9}, {%0,%1,%2,%3};"      \
                 : "+f"((d)[0]), "+f"((d)[1]), "+f"((d)[2]), "+f"((d)[3])     \
                 : "r"((a)[0]), "r"((a)[1]), "r"((a)[2]), "r"((a)[3]),        \
                   "r"(b0), "r"(b1))

#define MMA_F16(d, a, b0, b1)                                                 \
    asm volatile("mma.sync.aligned.m16n8k16.row.col.f32.f16.f16.f32 "         \
                 "{%0,%1,%2,%3}, {%4,%5,%6,%7}, {%8,%9}, {%0,%1,%2,%3};"      \
                 : "+f"((d)[0]), "+f"((d)[1]), "+f"((d)[2]), "+f"((d)[3])     \
                 : "r"((a)[0]), "r"((a)[1]), "r"((a)[2]), "r"((a)[3]),        \
                   "r"(b0), "r"(b1))

#define CP16(dst, src)                                                        \
    asm volatile("cp.async.cg.shared.global [%0], [%1], 16;"                  \
                 :: "r"(dst), "l"(src))
#define CP_COMMIT() asm volatile("cp.async.commit_group;" ::: "memory")
#define CP_WAIT1()  asm volatile("cp.async.wait_group 1;" ::: "memory")
#define CP_WAIT0()  asm volatile("cp.async.wait_group 0;" ::: "memory")

// Fast exp on the fma pipe (no MUFU); rel err ~2.4e-6
__device__ __forceinline__ float fexp(float x)
{
    x = fmaxf(x, -87.0f);
    float y = x * 1.4426950408889634f;
    float t = y + 12582912.0f;
    int   i = __float_as_int(t) - 0x4B400000;
    float f = y - (t - 12582912.0f);
    float p = 1.3333558146e-3f;
    p = fmaf(p, f, 9.6181291076e-3f);
    p = fmaf(p, f, 5.5504108664e-2f);
    p = fmaf(p, f, 2.4022650696e-1f);
    p = fmaf(p, f, 6.9314718056e-1f);
    p = fmaf(p, f, 1.0f);
    return __int_as_float(__float_as_int(p) + (i << 23));
}

__device__ __forceinline__ void bf16split4(const float* v, uint32_t& hi2, uint32_t& hi2b,
                                           uint32_t& lo2, uint32_t& lo2b)
{
    __nv_bfloat16 h[4], l[4];
#pragma unroll
    for (int j = 0; j < 4; j++) {
        h[j] = __float2bfloat16(v[j]);
        l[j] = __float2bfloat16(v[j] - __bfloat162float(h[j]));
    }
    hi2  = (uint32_t)*(uint16_t*)&h[0] | ((uint32_t)*(uint16_t*)&h[1] << 16);
    hi2b = (uint32_t)*(uint16_t*)&h[2] | ((uint32_t)*(uint16_t*)&h[3] << 16);
    lo2  = (uint32_t)*(uint16_t*)&l[0] | ((uint32_t)*(uint16_t*)&l[1] << 16);
    lo2b = (uint32_t)*(uint16_t*)&l[2] | ((uint32_t)*(uint16_t*)&l[3] << 16);
}

__device__ __forceinline__ void f16split4(const float* v, uint32_t& hi2, uint32_t& hi2b,
                                          uint32_t& lo2, uint32_t& lo2b)
{
    __half h[4], l[4];
#pragma unroll
    for (int j = 0; j < 4; j++) {
        h[j] = __float2half(v[j]);
        l[j] = __float2half(v[j] - __half2float(h[j]));
    }
    hi2  = (uint32_t)*(uint16_t*)&h[0] | ((uint32_t)*(uint16_t*)&h[1] << 16);
    hi2b = (uint32_t)*(uint16_t*)&h[2] | ((uint32_t)*(uint16_t*)&h[3] << 16);
    lo2  = (uint32_t)*(uint16_t*)&l[0] | ((uint32_t)*(uint16_t*)&l[1] << 16);
    lo2b = (uint32_t)*(uint16_t*)&l[2] | ((uint32_t)*(uint16_t*)&l[3] << 16);
}

__device__ __forceinline__ uint32_t h2pack(float a, float b)
{
    __half2 hh = __floats2half2_rn(a, b);
    return *reinterpret_cast<uint32_t*>(&hh);
}

// ---------------------------------------------------------------------------
// fp32 -> bf16 hi/lo split (elementwise, float4) — QKV inputs
// ---------------------------------------------------------------------------
__global__ __launch_bounds__(256)
void split_kernel(const float* __restrict__ src, __nv_bfloat16* __restrict__ h,
                  __nv_bfloat16* __restrict__ l)
{
    const size_t i = ((size_t)blockIdx.x * 256 + threadIdx.x) * 4;
    float4 v4 = *reinterpret_cast<const float4*>(src + i);
    float v[4] = {v4.x, v4.y, v4.z, v4.w};
    uint32_t h0, h1, l0, l1;
    bf16split4(v, h0, h1, l0, l1);
    *reinterpret_cast<uint2*>(h + i) = make_uint2(h0, h1);
    *reinterpret_cast<uint2*>(l + i) = make_uint2(l0, l1);
}

// ---------------------------------------------------------------------------
// MMA kernels: CTA tile 128x128, BK=32, 256 threads (8 warps 64x32).
// PITCH=80 smem rows; cp.async double buffering.
// ---------------------------------------------------------------------------
#define PITCH 80
#define TILEB (128 * PITCH)            // 10240
#define BUF3  (3 * TILEB)              // 2-term kernels: Ah|Al|Bh
#define BUF4  (4 * TILEB)              // 3-term kernel:  Ah|Al|Bh|Bl
#define SMEM3 (2 * BUF3)               // 61440
#define SMEM4 (2 * BUF4)               // 81920

#define CPSTAGE2(dh, dl, srch, srcl, ld, kc)                                  \
    _Pragma("unroll")                                                         \
    for (int t = 0; t < 2; t++) {                                             \
        const int q = tid + t * 256;                                          \
        const int row = q >> 2, seg = q & 3;                                  \
        const uint32_t so = row * PITCH + seg * 16;                           \
        const size_t go = (size_t)row * (ld) + (size_t)(kc) * 32 + seg * 8;   \
        CP16((dh) + so, (srch) + go);                                         \
        CP16((dl) + so, (srcl) + go);                                         \
    }

#define CPSTAGE1(dh, srch, ld, kc)                                            \
    _Pragma("unroll")                                                         \
    for (int t = 0; t < 2; t++) {                                             \
        const int q = tid + t * 256;                                          \
        const int row = q >> 2, seg = q & 3;                                  \
        const uint32_t so = row * PITCH + seg * 16;                           \
        const size_t go = (size_t)row * (ld) + (size_t)(kc) * 32 + seg * 8;   \
        CP16((dh) + so, (srch) + go);                                         \
    }

// 2-term fp16: D += Ah*Bh + Al*Bh
#define COMPUTE2(aH, aL, bH)                                                  \
    _Pragma("unroll")                                                         \
    for (int kk = 0; kk < 2; kk++) {                                          \
        uint32_t bhf[2][4];                                                   \
        LDSM4(bhf[0], (bH) + relB + kk * 32);                                 \
        LDSM4(bhf[1], (bH) + relB + 16 * PITCH + kk * 32);                    \
        _Pragma("unroll")                                                     \
        for (int mt = 0; mt < 4; mt++) {                                      \
            uint32_t ah[4], al[4];                                            \
            LDSM4(ah, (aH) + relA + mt * 16 * PITCH + kk * 32);               \
            LDSM4(al, (aL) + relA + mt * 16 * PITCH + kk * 32);               \
            _Pragma("unroll")                                                 \
            for (int g = 0; g < 2; g++) {                                     \
                _Pragma("unroll")                                             \
                for (int h = 0; h < 2; h++) {                                 \
                    float* acc = d[mt * 4 + g * 2 + h];                       \
                    MMA_F16(acc, ah, bhf[g][h], bhf[g][h + 2]);               \
                    MMA_F16(acc, al, bhf[g][h], bhf[g][h + 2]);               \
                }                                                             \
            }                                                                 \
        }                                                                     \
    }

// 3-term bf16: D += Ah*Bh + Ah*Bl + Al*Bh
#define COMPUTE3(aH, aL, bH, bL)                                              \
    _Pragma("unroll")                                                         \
    for (int kk = 0; kk < 2; kk++) {                                          \
        uint32_t bhf[2][4], blf[2][4];                                        \
        LDSM4(bhf[0], (bH) + relB + kk * 32);                                 \
        LDSM4(bhf[1], (bH) + relB + 16 * PITCH + kk * 32);                    \
        LDSM4(blf[0], (bL) + relB + kk * 32);                                 \
        LDSM4(blf[1], (bL) + relB + 16 * PITCH + kk * 32);                    \
        _Pragma("unroll")                                                     \
        for (int mt = 0; mt < 4; mt++) {                                      \
            uint32_t ah[4], al[4];                                            \
            LDSM4(ah, (aH) + relA + mt * 16 * PITCH + kk * 32);               \
            LDSM4(al, (aL) + relA + mt * 16 * PITCH + kk * 32);               \
            _Pragma("unroll")                                                 \
            for (int g = 0; g < 2; g++) {                                     \
                _Pragma("unroll")                                             \
                for (int h = 0; h < 2; h++) {                                 \
                    float* acc = d[mt * 4 + g * 2 + h];                       \
                    MMA_BF16(acc, ah, bhf[g][h], bhf[g][h + 2]);              \
                    MMA_BF16(acc, ah, blf[g][h], blf[g][h + 2]);              \
                    MMA_BF16(acc, al, bhf[g][h], bhf[g][h + 2]);              \
                }                                                             \
            }                                                                 \
        }                                                                     \
    }

#define MM_PROLOGUE()                                                         \
    extern __shared__ __align__(16) uint8_t smem[];                           \
    const uint32_t sb = smem_u32(smem);                                       \
    const int tid = threadIdx.x;                                              \
    const int lane = tid & 31;                                                \
    const int wm = (tid >> 5) & 1;                                            \
    const int wn = tid >> 6;                                                  \
    const uint32_t lrow = lane & 15, lhalf = lane >> 4;                       \
    const uint32_t relA = (wm * 64 + lrow) * PITCH + lhalf * 16;              \
    const uint32_t relB = (wn * 32 + lrow) * PITCH + lhalf * 16;              \
    float d[16][4];                                                           \
    _Pragma("unroll")                                                         \
    for (int i = 0; i < 16; i++)                                              \
        _Pragma("unroll")                                                     \
        for (int j = 0; j < 4; j++) d[i][j] = 0.0f;

// 3-tile buffers (2-term kernels)
#define B3_AH(bi) (sb + (bi) * BUF3)
#define B3_AL(bi) (sb + (bi) * BUF3 + TILEB)
#define B3_BH(bi) (sb + (bi) * BUF3 + 2 * TILEB)
// 4-tile buffers (3-term kernel)
#define B4_AH(bi) (sb + (bi) * BUF4)
#define B4_AL(bi) (sb + (bi) * BUF4 + TILEB)
#define B4_BH(bi) (sb + (bi) * BUF4 + 2 * TILEB)
#define B4_BL(bi) (sb + (bi) * BUF4 + 3 * TILEB)

// ---------------------------------------------------------------------------
// E = Q K^T / 16 (fp16 2-term) with fused per-tile column softmax partials
// ---------------------------------------------------------------------------
__global__ __launch_bounds__(256, 2)
void mm_e(float* __restrict__ Ef)
{
    MM_PROLOGUE();
    const int b = blockIdx.z;
    const int n0 = blockIdx.x * 128, m0 = blockIdx.y * 128;

    const __half* pAh = g_Qh + (size_t)b * LL * DD + (size_t)m0 * DD;
    const __half* pAl = g_Ql + (size_t)b * LL * DD + (size_t)m0 * DD;
    const __half* pBh = g_Kh + (size_t)b * LL * DD + (size_t)n0 * DD;

    const int NCH = DD / 32;   // 8
    CPSTAGE2(B3_AH(0), B3_AL(0), pAh, pAl, DD, 0);
    CPSTAGE1(B3_BH(0), pBh, DD, 0);
    CP_COMMIT();
    CPSTAGE2(B3_AH(1), B3_AL(1), pAh, pAl, DD, 1);
    CPSTAGE1(B3_BH(1), pBh, DD, 1);
    CP_COMMIT();

    for (int kc = 0; kc < NCH; kc++) {
        const int bi = kc & 1;
        if (kc == NCH - 1) { CP_WAIT0(); } else { CP_WAIT1(); }
        __syncthreads();
        COMPUTE2(B3_AH(bi), B3_AL(bi), B3_BH(bi));
        __syncthreads();
        if (kc + 2 < NCH) {
            CPSTAGE2(B3_AH(bi), B3_AL(bi), pAh, pAl, DD, kc + 2);
            CPSTAGE1(B3_BH(bi), pBh, DD, kc + 2);
            CP_COMMIT();
        }
    }

#pragma unroll
    for (int i = 0; i < 16; i++)
#pragma unroll
        for (int j = 0; j < 4; j++) d[i][j] *= (1.0f / 16.0f);

    float* Cb = Ef + (size_t)b * LL * LL;
#pragma unroll
    for (int mt = 0; mt < 4; mt++) {
#pragma unroll
        for (int ni = 0; ni < 4; ni++) {
            const float* acc = d[mt * 4 + ni];
            const int row = m0 + wm * 64 + mt * 16 + (lane >> 2);
            const int col = n0 + wn * 32 + ni * 8 + (lane & 3) * 2;
            *reinterpret_cast<float2*>(&Cb[(size_t)row * LL + col]) =
                make_float2(acc[0], acc[1]);
            *reinterpret_cast<float2*>(&Cb[(size_t)(row + 8) * LL + col]) =
                make_float2(acc[2], acc[3]);
        }
    }

    float* sMx = reinterpret_cast<float*>(smem);
    float* sSm = reinterpret_cast<float*>(smem) + 256;
    __syncthreads();
#pragma unroll
    for (int ni = 0; ni < 4; ni++) {
#pragma unroll
        for (int p = 0; p < 2; p++) {
            float mx = -1e30f;
#pragma unroll
            for (int mt = 0; mt < 4; mt++)
                mx = fmaxf(mx, fmaxf(d[mt * 4 + ni][p], d[mt * 4 + ni][p + 2]));
            float sm = 0.0f;
#pragma unroll
            for (int mt = 0; mt < 4; mt++)
                sm += fexp(d[mt * 4 + ni][p] - mx) + fexp(d[mt * 4 + ni][p + 2] - mx);
#pragma unroll
            for (int off = 4; off < 32; off <<= 1) {
                float omx = __shfl_xor_sync(0xFFFFFFFFu, mx, off);
                float osm = __shfl_xor_sync(0xFFFFFFFFu, sm, off);
                float nm = fmaxf(mx, omx);
                sm = sm * fexp(mx - nm) + osm * fexp(omx - nm);
                mx = nm;
            }
            if ((lane >> 2) == 0) {
                const int c = wn * 32 + ni * 8 + (lane & 3) * 2 + p;
                sMx[wm * 128 + c] = mx;
                sSm[wm * 128 + c] = sm;
            }
        }
    }
    __syncthreads();
    if (tid < 128) {
        float m0v = sMx[tid], m1v = sMx[128 + tid];
        float nm = fmaxf(m0v, m1v);
        float s = sSm[tid] * fexp(m0v - nm) + sSm[128 + tid] * fexp(m1v - nm);
        g_pm[b][blockIdx.y][n0 + tid] = nm;
        g_ps[b][blockIdx.y][n0 + tid] = s;
    }
}

// ---------------------------------------------------------------------------
// C = A V^T (fp16 2-term): A = exp(E - m[k])*is[k] staged on the fly;
// n-tile x writes A fp32 for k-chunks [x*32, x*32+32).
// ---------------------------------------------------------------------------
__global__ __launch_bounds__(256, 2)
void mm_av(const float* __restrict__ Ef, float* __restrict__ Aout,
           float* __restrict__ Cout)
{
    MM_PROLOGUE();
    const int b = blockIdx.z;
    const int n0 = blockIdx.x * 128, m0 = blockIdx.y * 128;

    const float*  pE  = Ef + (size_t)b * LL * LL + (size_t)m0 * LL;
    float*        pA  = Aout + (size_t)b * LL * LL + (size_t)m0 * LL;
    const __half* pBh = g_VTh + (size_t)b * DD * LL + (size_t)n0 * LL;

    const int NCH = LL / 32;   // 64
    const int wlo = blockIdx.x * 32, whi = wlo + 32;

    float4 e4[4];
#pragma unroll
    for (int t = 0; t < 4; t++) {
        const int q = tid + t * 256;
        const int row = q >> 3, seg = q & 7;
        e4[t] = *reinterpret_cast<const float4*>(pE + (size_t)row * LL + seg * 4);
    }
    CPSTAGE1(B3_BH(0), pBh, LL, 0);
    CP_COMMIT();
    CPSTAGE1(B3_BH(1), pBh, LL, 1);
    CP_COMMIT();

    for (int kc = 0; kc < NCH; kc++) {
        const int bi = kc & 1;
        const bool wA = (kc >= wlo) && (kc < whi);
#pragma unroll
        for (int t = 0; t < 4; t++) {
            const int q = tid + t * 256;
            const int row = q >> 3, seg = q & 7;
            const int k = kc * 32 + seg * 4;
            float4 m4 = *reinterpret_cast<const float4*>(&g_m[b][k]);
            float4 i4 = *reinterpret_cast<const float4*>(&g_is[b][k]);
            float v[4];
            v[0] = fexp(e4[t].x - m4.x) * i4.x;
            v[1] = fexp(e4[t].y - m4.y) * i4.y;
            v[2] = fexp(e4[t].z - m4.z) * i4.z;
            v[3] = fexp(e4[t].w - m4.w) * i4.w;
            if (wA)
                *reinterpret_cast<float4*>(pA + (size_t)row * LL + k) =
                    make_float4(v[0], v[1], v[2], v[3]);
            uint32_t h0, h1, l0, l1;
            f16split4(v, h0, h1, l0, l1);
            const uint32_t so = row * PITCH + seg * 8;
            *reinterpret_cast<uint2*>(smem + bi * BUF3 + so) = make_uint2(h0, h1);
            *reinterpret_cast<uint2*>(smem + bi * BUF3 + TILEB + so) = make_uint2(l0, l1);
        }
        if (kc == NCH - 1) { CP_WAIT0(); } else { CP_WAIT1(); }
        __syncthreads();
        if (kc + 1 < NCH) {
#pragma unroll
            for (int t = 0; t < 4; t++) {
                const int q = tid + t * 256;
                const int row = q >> 3, seg = q & 7;
                e4[t] = *reinterpret_cast<const float4*>(
                    pE + (size_t)row * LL + (size_t)(kc + 1) * 32 + seg * 4);
            }
        }
        COMPUTE2(B3_AH(bi), B3_AL(bi), B3_BH(bi));
        __syncthreads();
        if (kc + 2 < NCH) {
            CPSTAGE1(B3_BH(bi), pBh, LL, kc + 2);
            CP_COMMIT();
        }
    }

    float* Cb = Cout + (size_t)b * 2 * LL * DD;
#pragma unroll
    for (int mt = 0; mt < 4; mt++) {
#pragma unroll
        for (int ni = 0; ni < 4; ni++) {
            const float* acc = d[mt * 4 + ni];
            const int row = m0 + wm * 64 + mt * 16 + (lane >> 2);
            const int col = n0 + wn * 32 + ni * 8 + (lane & 3) * 2;
            *reinterpret_cast<float2*>(&Cb[(size_t)row * DD + col]) =
                make_float2(acc[0], acc[1]);
            *reinterpret_cast<float2*>(&Cb[(size_t)(row + 8) * DD + col]) =
                make_float2(acc[2], acc[3]);
        }
    }
}

// ---------------------------------------------------------------------------
// QKV (bf16 3-term): {Q,K,V}[r,n] = x[r,:].W[n,:] + b[n]
// ---------------------------------------------------------------------------
__global__ __launch_bounds__(256, 2)
void mm_qkv(const float* __restrict__ bq, const float* __restrict__ bk,
            const float* __restrict__ bv, float* __restrict__ Sp)
{
    MM_PROLOGUE();
    const int w = blockIdx.z;
    const int n0 = blockIdx.x * 128, m0 = blockIdx.y * 128;

    const __nv_bfloat16* pAh = g_xh + (size_t)m0 * DD;
    const __nv_bfloat16* pAl = g_xl + (size_t)m0 * DD;
    const __nv_bfloat16* pBh = g_Wh[w] + (size_t)n0 * DD;
    const __nv_bfloat16* pBl = g_Wl[w] + (size_t)n0 * DD;

    const int NCH = DD / 32;
    CPSTAGE2(B4_AH(0), B4_AL(0), pAh, pAl, DD, 0);
    CPSTAGE2(B4_BH(0), B4_BL(0), pBh, pBl, DD, 0);
    CP_COMMIT();
    CPSTAGE2(B4_AH(1), B4_AL(1), pAh, pAl, DD, 1);
    CPSTAGE2(B4_BH(1), B4_BL(1), pBh, pBl, DD, 1);
    CP_COMMIT();

    for (int kc = 0; kc < NCH; kc++) {
        const int bi = kc & 1;
        if (kc == NCH - 1) { CP_WAIT0(); } else { CP_WAIT1(); }
        __syncthreads();
        COMPUTE3(B4_AH(bi), B4_AL(bi), B4_BH(bi), B4_BL(bi));
        __syncthreads();
        if (kc + 2 < NCH) {
            CPSTAGE2(B4_AH(bi), B4_AL(bi), pAh, pAl, DD, kc + 2);
            CPSTAGE2(B4_BH(bi), B4_BL(bi), pBh, pBl, DD, kc + 2);
            CP_COMMIT();
        }
    }

    const float* bias = (w == 0) ? bq : (w == 1) ? bk : bv;

#pragma unroll
    for (int mt = 0; mt < 4; mt++) {
#pragma unroll
        for (int ni = 0; ni < 4; ni++) {
            float* acc = d[mt * 4 + ni];
            const int row = m0 + wm * 64 + mt * 16 + (lane >> 2);
            const int col = n0 + wn * 32 + ni * 8 + (lane & 3) * 2;
            const float b0 = bias[col], b1 = bias[col + 1];
            float v0 = acc[0] + b0, v1 = acc[1] + b1;
            float v2 = acc[2] + b0, v3 = acc[3] + b1;
            const int bb0 = row >> 11, l0i = row & 2047;
            const int bb1 = (row + 8) >> 11, l1i = (row + 8) & 2047;
            const size_t o0 = (size_t)row * DD + col;
            const size_t o1 = (size_t)(row + 8) * DD + col;
            if (w == 0) {
                float* q0 = Sp + (size_t)bb0 * 2 * LL * DD + (size_t)l0i * DD + col;
                float* q1 = Sp + (size_t)bb1 * 2 * LL * DD + (size_t)l1i * DD + col;
                *reinterpret_cast<float2*>(q0) = make_float2(v0, v1);
                *reinterpret_cast<float2*>(q1) = make_float2(v2, v3);
                __half h0 = __float2half(v0), h1 = __float2half(v1);
                __half h2 = __float2half(v2), h3 = __float2half(v3);
                *reinterpret_cast<uint32_t*>(&g_Qh[o0]) = h2pack(v0, v1);
                *reinterpret_cast<uint32_t*>(&g_Qh[o1]) = h2pack(v2, v3);
                *reinterpret_cast<uint32_t*>(&g_Ql[o0]) =
                    h2pack(v0 - __half2float(h0), v1 - __half2float(h1));
                *reinterpret_cast<uint32_t*>(&g_Ql[o1]) =
                    h2pack(v2 - __half2float(h2), v3 - __half2float(h3));
            } else if (w == 1) {
                *reinterpret_cast<uint32_t*>(&g_Kh[o0]) = h2pack(v0, v1);
                *reinterpret_cast<uint32_t*>(&g_Kh[o1]) = h2pack(v2, v3);
            } else {
                float* p0 = g_V + o0;
                float* p1 = g_V + o1;
                *reinterpret_cast<float2*>(p0) = make_float2(v0, v1);
                *reinterpret_cast<float2*>(p1) = make_float2(v2, v3);
            }
        }
    }
}

// ---------------------------------------------------------------------------
// V [b][l][d] fp32 -> VT hi fp16 [b][d][l]
// ---------------------------------------------------------------------------
__global__ __launch_bounds__(256)
void vtrans_kernel(const float* __restrict__ V)
{
    __shared__ float t[32][33];
    const int b = blockIdx.z;
    const int l0 = blockIdx.x * 32, d0 = blockIdx.y * 32;
    const int tx = threadIdx.x & 31, ty = threadIdx.x >> 5;

    const float* Vb = V + (size_t)b * LL * DD;
#pragma unroll
    for (int i = 0; i < 4; i++)
        t[ty + i * 8][tx] = Vb[(size_t)(l0 + ty + i * 8) * DD + d0 + tx];
    __syncthreads();

    __half* Th = g_VTh + (size_t)b * DD * LL;
#pragma unroll
    for (int i = 0; i < 4; i++)
        Th[(size_t)(d0 + ty + i * 8) * LL + l0 + tx] = __float2half(t[tx][ty + i * 8]);
}

// ---------------------------------------------------------------------------
// Softmax combine (16 partials per column)
// ---------------------------------------------------------------------------
__global__ __launch_bounds__(256)
void softmax_combine()
{
    const int b = blockIdx.y;
    const int col = blockIdx.x * 256 + threadIdx.x;
    float m = -1e30f;
#pragma unroll
    for (int c = 0; c < 16; c++) m = fmaxf(m, g_pm[b][c][col]);
    float s = 0.f;
#pragma unroll
    for (int c = 0; c < 16; c++) s += g_ps[b][c][col] * fexp(g_pm[b][c][col] - m);
    g_m[b][col] = m;
    g_is[b][col] = 1.0f / s;
}

// ---------------------------------------------------------------------------
// Launch
// ---------------------------------------------------------------------------
extern "C" void kernel_launch(void* const* d_in, const int* in_sizes, int n_in,
                              void* d_out, int out_size)
{
    const float* x  = (const float*)d_in[0];
    const float* Wq = (const float*)d_in[1];
    const float* bq = (const float*)d_in[2];
    const float* Wk = (const float*)d_in[3];
    const float* bk = (const float*)d_in[4];
    const float* Wv = (const float*)d_in[5];
    const float* bv = (const float*)d_in[6];

    float* out  = (float*)d_out;
    float* Sp   = out;                                  // [B, 2L, D]
    float* Aout = out + (size_t)BB * 2 * LL * DD;       // [B, L, L]

    float *gV, *gE;
    __nv_bfloat16 *gxh, *gxl, *gWh, *gWl;
    cudaGetSymbolAddress((void**)&gV,  g_V);
    cudaGetSymbolAddress((void**)&gE,  g_E);
    cudaGetSymbolAddress((void**)&gxh, g_xh);
    cudaGetSymbolAddress((void**)&gxl, g_xl);
    cudaGetSymbolAddress((void**)&gWh, g_Wh);
    cudaGetSymbolAddress((void**)&gWl, g_Wl);

    cudaFuncSetAttribute(mm_e,   cudaFuncAttributeMaxDynamicSharedMemorySize, SMEM3);
    cudaFuncSetAttribute(mm_av,  cudaFuncAttributeMaxDynamicSharedMemorySize, SMEM3);
    cudaFuncSetAttribute(mm_qkv, cudaFuncAttributeMaxDynamicSharedMemorySize, SMEM4);

    // 1) split x and W into bf16 hi/lo
    const size_t nx = (size_t)BB * LL * DD;
    split_kernel<<<(unsigned)(nx / 1024), 256>>>(x, gxh, gxl);
    split_kernel<<<DD * DD / 1024, 256>>>(Wq, gWh, gWl);
    split_kernel<<<DD * DD / 1024, 256>>>(Wk, gWh + DD * DD, gWl + DD * DD);
    split_kernel<<<DD * DD / 1024, 256>>>(Wv, gWh + 2 * DD * DD, gWl + 2 * DD * DD);

    // 2) QKV on tensor cores (bf16 3-term)
    mm_qkv<<<dim3(2, (BB * LL) / 128, 3), 256, SMEM4>>>(bq, bk, bv, Sp);

    // 3) V -> VT hi fp16
    vtrans_kernel<<<dim3(LL / 32, DD / 32, BB), 256>>>(gV);

    // 4) E = Q K^T / 16 (fp16 2-term) with fused softmax partials
    mm_e<<<dim3(LL / 128, LL / 128, BB), 256, SMEM3>>>(gE);

    // 5) softmax finalize
    softmax_combine<<<dim3(LL / 256, BB), 256>>>();

    // 6) C = A V (fp16 2-term; A from E on the fly; n-tiles split A writes)
    mm_av<<<dim3(DD / 128, LL / 128, BB), 256, SMEM3>>>(gE, Aout, Sp + (size_t)LL * DD);

    (void)in_sizes; (void)n_in; (void)out_size;
}

// round 9
// speedup vs baseline: 5.1393x; 1.3293x over previous
#include <cuda_runtime.h>
#include <cuda_bf16.h>
#include <cuda_fp16.h>
#include <cstdint>
#include <cstddef>

// Problem constants
#define BB 8
#define LL 2048
#define DD 256

// ---------------------------------------------------------------------------
// Scratch (__device__ globals; no allocation allowed)
// ---------------------------------------------------------------------------
__device__ float          g_V [(size_t)BB * LL * DD];      // V fp32 (transpose src)
__device__ float          g_E [(size_t)BB * LL * LL];      // E fp32
__device__ __nv_bfloat16  g_xh[(size_t)BB * LL * DD];      // x hi/lo (bf16, QKV 3-term)
__device__ __nv_bfloat16  g_xl[(size_t)BB * LL * DD];
__device__ __nv_bfloat16  g_Wh[3][DD * DD];
__device__ __nv_bfloat16  g_Wl[3][DD * DD];
__device__ __half         g_Qh[(size_t)BB * LL * DD];      // fp16 single operands
__device__ __half         g_Kh[(size_t)BB * LL * DD];
__device__ __half         g_VTh[(size_t)BB * DD * LL];     // V^T fp16 [b][d][l]
__device__ float g_pm[BB][16][LL];
__device__ float g_ps[BB][16][LL];
__device__ float g_m [BB][LL];
__device__ float g_is[BB][LL];

// ---------------------------------------------------------------------------
// Helpers
// ---------------------------------------------------------------------------
__device__ __forceinline__ uint32_t smem_u32(const void* p) {
    uint32_t a;
    asm("{ .reg .u64 t; cvta.to.shared.u64 t, %1; cvt.u32.u64 %0, t; }"
        : "=r"(a) : "l"(p));
    return a;
}

#define LDSM4(r, addr)                                                        \
    asm volatile("ldmatrix.sync.aligned.m8n8.x4.shared.b16 {%0,%1,%2,%3}, [%4];" \
                 : "=r"((r)[0]), "=r"((r)[1]), "=r"((r)[2]), "=r"((r)[3])     \
                 : "r"(addr))

#define MMA_BF16(d, a, b0, b1)                                                \
    asm volatile("mma.sync.aligned.m16n8k16.row.col.f32.bf16.bf16.f32 "       \
                 "{%0,%1,%2,%3}, {%4,%5,%6,%7}, {%8,%9}, {%0,%1,%2,%3};"      \
                 : "+f"((d)[0]), "+f"((d)[1]), "+f"((d)[2]), "+f"((d)[3])     \
                 : "r"((a)[0]), "r"((a)[1]), "r"((a)[2]), "r"((a)[3]),        \
                   "r"(b0), "r"(b1))

#define MMA_F16(d, a, b0, b1)                                                 \
    asm volatile("mma.sync.aligned.m16n8k16.row.col.f32.f16.f16.f32 "         \
                 "{%0,%1,%2,%3}, {%4,%5,%6,%7}, {%8,%9}, {%0,%1,%2,%3};"      \
                 : "+f"((d)[0]), "+f"((d)[1]), "+f"((d)[2]), "+f"((d)[3])     \
                 : "r"((a)[0]), "r"((a)[1]), "r"((a)[2]), "r"((a)[3]),        \
                   "r"(b0), "r"(b1))

#define CP16(dst, src)                                                        \
    asm volatile("cp.async.cg.shared.global [%0], [%1], 16;"                  \
                 :: "r"(dst), "l"(src))
#define CP_COMMIT() asm volatile("cp.async.commit_group;" ::: "memory")
#define CP_WAIT1()  asm volatile("cp.async.wait_group 1;" ::: "memory")
#define CP_WAIT0()  asm volatile("cp.async.wait_group 0;" ::: "memory")

// Fast exp on the fma pipe (no MUFU); rel err ~2.4e-6
__device__ __forceinline__ float fexp(float x)
{
    x = fmaxf(x, -87.0f);
    float y = x * 1.4426950408889634f;
    float t = y + 12582912.0f;
    int   i = __float_as_int(t) - 0x4B400000;
    float f = y - (t - 12582912.0f);
    float p = 1.3333558146e-3f;
    p = fmaf(p, f, 9.6181291076e-3f);
    p = fmaf(p, f, 5.5504108664e-2f);
    p = fmaf(p, f, 2.4022650696e-1f);
    p = fmaf(p, f, 6.9314718056e-1f);
    p = fmaf(p, f, 1.0f);
    return __int_as_float(__float_as_int(p) + (i << 23));
}

__device__ __forceinline__ void bf16split4(const float* v, uint32_t& hi2, uint32_t& hi2b,
                                           uint32_t& lo2, uint32_t& lo2b)
{
    __nv_bfloat16 h[4], l[4];
#pragma unroll
    for (int j = 0; j < 4; j++) {
        h[j] = __float2bfloat16(v[j]);
        l[j] = __float2bfloat16(v[j] - __bfloat162float(h[j]));
    }
    hi2  = (uint32_t)*(uint16_t*)&h[0] | ((uint32_t)*(uint16_t*)&h[1] << 16);
    hi2b = (uint32_t)*(uint16_t*)&h[2] | ((uint32_t)*(uint16_t*)&h[3] << 16);
    lo2  = (uint32_t)*(uint16_t*)&l[0] | ((uint32_t)*(uint16_t*)&l[1] << 16);
    lo2b = (uint32_t)*(uint16_t*)&l[2] | ((uint32_t)*(uint16_t*)&l[3] << 16);
}

__device__ __forceinline__ uint32_t h2pack(float a, float b)
{
    __half2 hh = __floats2half2_rn(a, b);
    return *reinterpret_cast<uint32_t*>(&hh);
}

// ---------------------------------------------------------------------------
// fp32 -> bf16 hi/lo split (elementwise, float4) — QKV inputs
// ---------------------------------------------------------------------------
__global__ __launch_bounds__(256)
void split_kernel(const float* __restrict__ src, __nv_bfloat16* __restrict__ h,
                  __nv_bfloat16* __restrict__ l)
{
    const size_t i = ((size_t)blockIdx.x * 256 + threadIdx.x) * 4;
    float4 v4 = *reinterpret_cast<const float4*>(src + i);
    float v[4] = {v4.x, v4.y, v4.z, v4.w};
    uint32_t h0, h1, l0, l1;
    bf16split4(v, h0, h1, l0, l1);
    *reinterpret_cast<uint2*>(h + i) = make_uint2(h0, h1);
    *reinterpret_cast<uint2*>(l + i) = make_uint2(l0, l1);
}

// ---------------------------------------------------------------------------
// MMA kernels: CTA tile 128x128, BK=32, 256 threads (8 warps 64x32).
// PITCH=80 smem rows; cp.async double buffering.
// ---------------------------------------------------------------------------
#define PITCH 80
#define TILEB (128 * PITCH)            // 10240
#define BUF2  (2 * TILEB)              // 1-term kernels: Ah|Bh
#define BUF4  (4 * TILEB)              // 3-term kernel:  Ah|Al|Bh|Bl
#define SMEM2 (2 * BUF2)               // 40960
#define SMEM4 (2 * BUF4)               // 81920

#define CPSTAGE2(dh, dl, srch, srcl, ld, kc)                                  \
    _Pragma("unroll")                                                         \
    for (int t = 0; t < 2; t++) {                                             \
        const int q = tid + t * 256;                                          \
        const int row = q >> 2, seg = q & 3;                                  \
        const uint32_t so = row * PITCH + seg * 16;                           \
        const size_t go = (size_t)row * (ld) + (size_t)(kc) * 32 + seg * 8;   \
        CP16((dh) + so, (srch) + go);                                         \
        CP16((dl) + so, (srcl) + go);                                         \
    }

#define CPSTAGE1(dh, srch, ld, kc)                                            \
    _Pragma("unroll")                                                         \
    for (int t = 0; t < 2; t++) {                                             \
        const int q = tid + t * 256;                                          \
        const int row = q >> 2, seg = q & 3;                                  \
        const uint32_t so = row * PITCH + seg * 16;                           \
        const size_t go = (size_t)row * (ld) + (size_t)(kc) * 32 + seg * 8;   \
        CP16((dh) + so, (srch) + go);                                         \
    }

// 1-term fp16: D += Ah*Bh
#define COMPUTE1(aH, bH)                                                      \
    _Pragma("unroll")                                                         \
    for (int kk = 0; kk < 2; kk++) {                                          \
        uint32_t bhf[2][4];                                                   \
        LDSM4(bhf[0], (bH) + relB + kk * 32);                                 \
        LDSM4(bhf[1], (bH) + relB + 16 * PITCH + kk * 32);                    \
        _Pragma("unroll")                                                     \
        for (int mt = 0; mt < 4; mt++) {                                      \
            uint32_t ah[4];                                                   \
            LDSM4(ah, (aH) + relA + mt * 16 * PITCH + kk * 32);               \
            _Pragma("unroll")                                                 \
            for (int g = 0; g < 2; g++) {                                     \
                _Pragma("unroll")                                             \
                for (int h = 0; h < 2; h++) {                                 \
                    float* acc = d[mt * 4 + g * 2 + h];                       \
                    MMA_F16(acc, ah, bhf[g][h], bhf[g][h + 2]);               \
                }                                                             \
            }                                                                 \
        }                                                                     \
    }

// 3-term bf16: D += Ah*Bh + Ah*Bl + Al*Bh
#define COMPUTE3(aH, aL, bH, bL)                                              \
    _Pragma("unroll")                                                         \
    for (int kk = 0; kk < 2; kk++) {                                          \
        uint32_t bhf[2][4], blf[2][4];                                        \
        LDSM4(bhf[0], (bH) + relB + kk * 32);                                 \
        LDSM4(bhf[1], (bH) + relB + 16 * PITCH + kk * 32);                    \
        LDSM4(blf[0], (bL) + relB + kk * 32);                                 \
        LDSM4(blf[1], (bL) + relB + 16 * PITCH + kk * 32);                    \
        _Pragma("unroll")                                                     \
        for (int mt = 0; mt < 4; mt++) {                                      \
            uint32_t ah[4], al[4];                                            \
            LDSM4(ah, (aH) + relA + mt * 16 * PITCH + kk * 32);               \
            LDSM4(al, (aL) + relA + mt * 16 * PITCH + kk * 32);               \
            _Pragma("unroll")                                                 \
            for (int g = 0; g < 2; g++) {                                     \
                _Pragma("unroll")                                             \
                for (int h = 0; h < 2; h++) {                                 \
                    float* acc = d[mt * 4 + g * 2 + h];                       \
                    MMA_BF16(acc, ah, bhf[g][h], bhf[g][h + 2]);              \
                    MMA_BF16(acc, ah, blf[g][h], blf[g][h + 2]);              \
                    MMA_BF16(acc, al, bhf[g][h], bhf[g][h + 2]);              \
                }                                                             \
            }                                                                 \
        }                                                                     \
    }

#define MM_PROLOGUE()                                                         \
    extern __shared__ __align__(16) uint8_t smem[];                           \
    const uint32_t sb = smem_u32(smem);                                       \
    const int tid = threadIdx.x;                                              \
    const int lane = tid & 31;                                                \
    const int wm = (tid >> 5) & 1;                                            \
    const int wn = tid >> 6;                                                  \
    const uint32_t lrow = lane & 15, lhalf = lane >> 4;                       \
    const uint32_t relA = (wm * 64 + lrow) * PITCH + lhalf * 16;              \
    const uint32_t relB = (wn * 32 + lrow) * PITCH + lhalf * 16;              \
    float d[16][4];                                                           \
    _Pragma("unroll")                                                         \
    for (int i = 0; i < 16; i++)                                              \
        _Pragma("unroll")                                                     \
        for (int j = 0; j < 4; j++) d[i][j] = 0.0f;

// 2-tile buffers (1-term kernels)
#define B2_AH(bi) (sb + (bi) * BUF2)
#define B2_BH(bi) (sb + (bi) * BUF2 + TILEB)
// 4-tile buffers (3-term kernel)
#define B4_AH(bi) (sb + (bi) * BUF4)
#define B4_AL(bi) (sb + (bi) * BUF4 + TILEB)
#define B4_BH(bi) (sb + (bi) * BUF4 + 2 * TILEB)
#define B4_BL(bi) (sb + (bi) * BUF4 + 3 * TILEB)

// ---------------------------------------------------------------------------
// E = Q K^T / 16 (fp16 1-term) with fused per-tile column softmax partials
// ---------------------------------------------------------------------------
__global__ __launch_bounds__(256, 2)
void mm_e(float* __restrict__ Ef)
{
    MM_PROLOGUE();
    const int b = blockIdx.z;
    const int n0 = blockIdx.x * 128, m0 = blockIdx.y * 128;

    const __half* pAh = g_Qh + (size_t)b * LL * DD + (size_t)m0 * DD;
    const __half* pBh = g_Kh + (size_t)b * LL * DD + (size_t)n0 * DD;

    const int NCH = DD / 32;   // 8
    CPSTAGE1(B2_AH(0), pAh, DD, 0);
    CPSTAGE1(B2_BH(0), pBh, DD, 0);
    CP_COMMIT();
    CPSTAGE1(B2_AH(1), pAh, DD, 1);
    CPSTAGE1(B2_BH(1), pBh, DD, 1);
    CP_COMMIT();

    for (int kc = 0; kc < NCH; kc++) {
        const int bi = kc & 1;
        if (kc == NCH - 1) { CP_WAIT0(); } else { CP_WAIT1(); }
        __syncthreads();
        COMPUTE1(B2_AH(bi), B2_BH(bi));
        __syncthreads();
        if (kc + 2 < NCH) {
            CPSTAGE1(B2_AH(bi), pAh, DD, kc + 2);
            CPSTAGE1(B2_BH(bi), pBh, DD, kc + 2);
            CP_COMMIT();
        }
    }

#pragma unroll
    for (int i = 0; i < 16; i++)
#pragma unroll
        for (int j = 0; j < 4; j++) d[i][j] *= (1.0f / 16.0f);

    float* Cb = Ef + (size_t)b * LL * LL;
#pragma unroll
    for (int mt = 0; mt < 4; mt++) {
#pragma unroll
        for (int ni = 0; ni < 4; ni++) {
            const float* acc = d[mt * 4 + ni];
            const int row = m0 + wm * 64 + mt * 16 + (lane >> 2);
            const int col = n0 + wn * 32 + ni * 8 + (lane & 3) * 2;
            *reinterpret_cast<float2*>(&Cb[(size_t)row * LL + col]) =
                make_float2(acc[0], acc[1]);
            *reinterpret_cast<float2*>(&Cb[(size_t)(row + 8) * LL + col]) =
                make_float2(acc[2], acc[3]);
        }
    }

    float* sMx = reinterpret_cast<float*>(smem);
    float* sSm = reinterpret_cast<float*>(smem) + 256;
    __syncthreads();
#pragma unroll
    for (int ni = 0; ni < 4; ni++) {
#pragma unroll
        for (int p = 0; p < 2; p++) {
            float mx = -1e30f;
#pragma unroll
            for (int mt = 0; mt < 4; mt++)
                mx = fmaxf(mx, fmaxf(d[mt * 4 + ni][p], d[mt * 4 + ni][p + 2]));
            float sm = 0.0f;
#pragma unroll
            for (int mt = 0; mt < 4; mt++)
                sm += fexp(d[mt * 4 + ni][p] - mx) + fexp(d[mt * 4 + ni][p + 2] - mx);
#pragma unroll
            for (int off = 4; off < 32; off <<= 1) {
                float omx = __shfl_xor_sync(0xFFFFFFFFu, mx, off);
                float osm = __shfl_xor_sync(0xFFFFFFFFu, sm, off);
                float nm = fmaxf(mx, omx);
                sm = sm * fexp(mx - nm) + osm * fexp(omx - nm);
                mx = nm;
            }
            if ((lane >> 2) == 0) {
                const int c = wn * 32 + ni * 8 + (lane & 3) * 2 + p;
                sMx[wm * 128 + c] = mx;
                sSm[wm * 128 + c] = sm;
            }
        }
    }
    __syncthreads();
    if (tid < 128) {
        float m0v = sMx[tid], m1v = sMx[128 + tid];
        float nm = fmaxf(m0v, m1v);
        float s = sSm[tid] * fexp(m0v - nm) + sSm[128 + tid] * fexp(m1v - nm);
        g_pm[b][blockIdx.y][n0 + tid] = nm;
        g_ps[b][blockIdx.y][n0 + tid] = s;
    }
}

// ---------------------------------------------------------------------------
// C = A V^T (fp16 1-term): A = exp(E - m[k])*is[k] staged as fp16 on the fly;
// n-tile x writes A fp32 for k-chunks [x*32, x*32+32).
// ---------------------------------------------------------------------------
__global__ __launch_bounds__(256, 2)
void mm_av(const float* __restrict__ Ef, float* __restrict__ Aout,
           float* __restrict__ Cout)
{
    MM_PROLOGUE();
    const int b = blockIdx.z;
    const int n0 = blockIdx.x * 128, m0 = blockIdx.y * 128;

    const float*  pE  = Ef + (size_t)b * LL * LL + (size_t)m0 * LL;
    float*        pA  = Aout + (size_t)b * LL * LL + (size_t)m0 * LL;
    const __half* pBh = g_VTh + (size_t)b * DD * LL + (size_t)n0 * LL;

    const int NCH = LL / 32;   // 64
    const int wlo = blockIdx.x * 32, whi = wlo + 32;

    float4 e4[4];
#pragma unroll
    for (int t = 0; t < 4; t++) {
        const int q = tid + t * 256;
        const int row = q >> 3, seg = q & 7;
        e4[t] = *reinterpret_cast<const float4*>(pE + (size_t)row * LL + seg * 4);
    }
    CPSTAGE1(B2_BH(0), pBh, LL, 0);
    CP_COMMIT();
    CPSTAGE1(B2_BH(1), pBh, LL, 1);
    CP_COMMIT();

    for (int kc = 0; kc < NCH; kc++) {
        const int bi = kc & 1;
        const bool wA = (kc >= wlo) && (kc < whi);
#pragma unroll
        for (int t = 0; t < 4; t++) {
            const int q = tid + t * 256;
            const int row = q >> 3, seg = q & 7;
            const int k = kc * 32 + seg * 4;
            float4 m4 = *reinterpret_cast<const float4*>(&g_m[b][k]);
            float4 i4 = *reinterpret_cast<const float4*>(&g_is[b][k]);
            float v[4];
            v[0] = fexp(e4[t].x - m4.x) * i4.x;
            v[1] = fexp(e4[t].y - m4.y) * i4.y;
            v[2] = fexp(e4[t].z - m4.z) * i4.z;
            v[3] = fexp(e4[t].w - m4.w) * i4.w;
            if (wA)
                *reinterpret_cast<float4*>(pA + (size_t)row * LL + k) =
                    make_float4(v[0], v[1], v[2], v[3]);
            const uint32_t so = row * PITCH + seg * 8;
            *reinterpret_cast<uint2*>(smem + bi * BUF2 + so) =
                make_uint2(h2pack(v[0], v[1]), h2pack(v[2], v[3]));
        }
        if (kc == NCH - 1) { CP_WAIT0(); } else { CP_WAIT1(); }
        __syncthreads();
        if (kc + 1 < NCH) {
#pragma unroll
            for (int t = 0; t < 4; t++) {
                const int q = tid + t * 256;
                const int row = q >> 3, seg = q & 7;
                e4[t] = *reinterpret_cast<const float4*>(
                    pE + (size_t)row * LL + (size_t)(kc + 1) * 32 + seg * 4);
            }
        }
        COMPUTE1(B2_AH(bi), B2_BH(bi));
        __syncthreads();
        if (kc + 2 < NCH) {
            CPSTAGE1(B2_BH(bi), pBh, LL, kc + 2);
            CP_COMMIT();
        }
    }

    float* Cb = Cout + (size_t)b * 2 * LL * DD;
#pragma unroll
    for (int mt = 0; mt < 4; mt++) {
#pragma unroll
        for (int ni = 0; ni < 4; ni++) {
            const float* acc = d[mt * 4 + ni];
            const int row = m0 + wm * 64 + mt * 16 + (lane >> 2);
            const int col = n0 + wn * 32 + ni * 8 + (lane & 3) * 2;
            *reinterpret_cast<float2*>(&Cb[(size_t)row * DD + col]) =
                make_float2(acc[0], acc[1]);
            *reinterpret_cast<float2*>(&Cb[(size_t)(row + 8) * DD + col]) =
                make_float2(acc[2], acc[3]);
        }
    }
}

// ---------------------------------------------------------------------------
// QKV (bf16 3-term): {Q,K,V}[r,n] = x[r,:].W[n,:] + b[n]
// ---------------------------------------------------------------------------
__global__ __launch_bounds__(256, 2)
void mm_qkv(const float* __restrict__ bq, const float* __restrict__ bk,
            const float* __restrict__ bv, float* __restrict__ Sp)
{
    MM_PROLOGUE();
    const int w = blockIdx.z;
    const int n0 = blockIdx.x * 128, m0 = blockIdx.y * 128;

    const __nv_bfloat16* pAh = g_xh + (size_t)m0 * DD;
    const __nv_bfloat16* pAl = g_xl + (size_t)m0 * DD;
    const __nv_bfloat16* pBh = g_Wh[w] + (size_t)n0 * DD;
    const __nv_bfloat16* pBl = g_Wl[w] + (size_t)n0 * DD;

    const int NCH = DD / 32;
    CPSTAGE2(B4_AH(0), B4_AL(0), pAh, pAl, DD, 0);
    CPSTAGE2(B4_BH(0), B4_BL(0), pBh, pBl, DD, 0);
    CP_COMMIT();
    CPSTAGE2(B4_AH(1), B4_AL(1), pAh, pAl, DD, 1);
    CPSTAGE2(B4_BH(1), B4_BL(1), pBh, pBl, DD, 1);
    CP_COMMIT();

    for (int kc = 0; kc < NCH; kc++) {
        const int bi = kc & 1;
        if (kc == NCH - 1) { CP_WAIT0(); } else { CP_WAIT1(); }
        __syncthreads();
        COMPUTE3(B4_AH(bi), B4_AL(bi), B4_BH(bi), B4_BL(bi));
        __syncthreads();
        if (kc + 2 < NCH) {
            CPSTAGE2(B4_AH(bi), B4_AL(bi), pAh, pAl, DD, kc + 2);
            CPSTAGE2(B4_BH(bi), B4_BL(bi), pBh, pBl, DD, kc + 2);
            CP_COMMIT();
        }
    }

    const float* bias = (w == 0) ? bq : (w == 1) ? bk : bv;

#pragma unroll
    for (int mt = 0; mt < 4; mt++) {
#pragma unroll
        for (int ni = 0; ni < 4; ni++) {
            float* acc = d[mt * 4 + ni];
            const int row = m0 + wm * 64 + mt * 16 + (lane >> 2);
            const int col = n0 + wn * 32 + ni * 8 + (lane & 3) * 2;
            const float b0 = bias[col], b1 = bias[col + 1];
            float v0 = acc[0] + b0, v1 = acc[1] + b1;
            float v2 = acc[2] + b0, v3 = acc[3] + b1;
            const int bb0 = row >> 11, l0i = row & 2047;
            const int bb1 = (row + 8) >> 11, l1i = (row + 8) & 2047;
            const size_t o0 = (size_t)row * DD + col;
            const size_t o1 = (size_t)(row + 8) * DD + col;
            if (w == 0) {
                float* q0 = Sp + (size_t)bb0 * 2 * LL * DD + (size_t)l0i * DD + col;
                float* q1 = Sp + (size_t)bb1 * 2 * LL * DD + (size_t)l1i * DD + col;
                *reinterpret_cast<float2*>(q0) = make_float2(v0, v1);
                *reinterpret_cast<float2*>(q1) = make_float2(v2, v3);
                *reinterpret_cast<uint32_t*>(&g_Qh[o0]) = h2pack(v0, v1);
                *reinterpret_cast<uint32_t*>(&g_Qh[o1]) = h2pack(v2, v3);
            } else if (w == 1) {
                *reinterpret_cast<uint32_t*>(&g_Kh[o0]) = h2pack(v0, v1);
                *reinterpret_cast<uint32_t*>(&g_Kh[o1]) = h2pack(v2, v3);
            } else {
                *reinterpret_cast<float2*>(g_V + o0) = make_float2(v0, v1);
                *reinterpret_cast<float2*>(g_V + o1) = make_float2(v2, v3);
            }
        }
    }
}

// ---------------------------------------------------------------------------
// V [b][l][d] fp32 -> VT fp16 [b][d][l]
// ---------------------------------------------------------------------------
__global__ __launch_bounds__(256)
void vtrans_kernel(const float* __restrict__ V)
{
    __shared__ float t[32][33];
    const int b = blockIdx.z;
    const int l0 = blockIdx.x * 32, d0 = blockIdx.y * 32;
    const int tx = threadIdx.x & 31, ty = threadIdx.x >> 5;

    const float* Vb = V + (size_t)b * LL * DD;
#pragma unroll
    for (int i = 0; i < 4; i++)
        t[ty + i * 8][tx] = Vb[(size_t)(l0 + ty + i * 8) * DD + d0 + tx];
    __syncthreads();

    __half* Th = g_VTh + (size_t)b * DD * LL;
#pragma unroll
    for (int i = 0; i < 4; i++)
        Th[(size_t)(d0 + ty + i * 8) * LL + l0 + tx] = __float2half(t[tx][ty + i * 8]);
}

// ---------------------------------------------------------------------------
// Softmax combine (16 partials per column)
// ---------------------------------------------------------------------------
__global__ __launch_bounds__(256)
void softmax_combine()
{
    const int b = blockIdx.y;
    const int col = blockIdx.x * 256 + threadIdx.x;
    float m = -1e30f;
#pragma unroll
    for (int c = 0; c < 16; c++) m = fmaxf(m, g_pm[b][c][col]);
    float s = 0.f;
#pragma unroll
    for (int c = 0; c < 16; c++) s += g_ps[b][c][col] * fexp(g_pm[b][c][col] - m);
    g_m[b][col] = m;
    g_is[b][col] = 1.0f / s;
}

// ---------------------------------------------------------------------------
// Launch
// ---------------------------------------------------------------------------
extern "C" void kernel_launch(void* const* d_in, const int* in_sizes, int n_in,
                              void* d_out, int out_size)
{
    const float* x  = (const float*)d_in[0];
    const float* Wq = (const float*)d_in[1];
    const float* bq = (const float*)d_in[2];
    const float* Wk = (const float*)d_in[3];
    const float* bk = (const float*)d_in[4];
    const float* Wv = (const float*)d_in[5];
    const float* bv = (const float*)d_in[6];

    float* out  = (float*)d_out;
    float* Sp   = out;                                  // [B, 2L, D]
    float* Aout = out + (size_t)BB * 2 * LL * DD;       // [B, L, L]

    float *gV, *gE;
    __nv_bfloat16 *gxh, *gxl, *gWh, *gWl;
    cudaGetSymbolAddress((void**)&gV,  g_V);
    cudaGetSymbolAddress((void**)&gE,  g_E);
    cudaGetSymbolAddress((void**)&gxh, g_xh);
    cudaGetSymbolAddress((void**)&gxl, g_xl);
    cudaGetSymbolAddress((void**)&gWh, g_Wh);
    cudaGetSymbolAddress((void**)&gWl, g_Wl);

    cudaFuncSetAttribute(mm_e,   cudaFuncAttributeMaxDynamicSharedMemorySize, SMEM2);
    cudaFuncSetAttribute(mm_av,  cudaFuncAttributeMaxDynamicSharedMemorySize, SMEM2);
    cudaFuncSetAttribute(mm_qkv, cudaFuncAttributeMaxDynamicSharedMemorySize, SMEM4);

    // 1) split x and W into bf16 hi/lo
    const size_t nx = (size_t)BB * LL * DD;
    split_kernel<<<(unsigned)(nx / 1024), 256>>>(x, gxh, gxl);
    split_kernel<<<DD * DD / 1024, 256>>>(Wq, gWh, gWl);
    split_kernel<<<DD * DD / 1024, 256>>>(Wk, gWh + DD * DD, gWl + DD * DD);
    split_kernel<<<DD * DD / 1024, 256>>>(Wv, gWh + 2 * DD * DD, gWl + 2 * DD * DD);

    // 2) QKV on tensor cores (bf16 3-term)
    mm_qkv<<<dim3(2, (BB * LL) / 128, 3), 256, SMEM4>>>(bq, bk, bv, Sp);

    // 3) V -> VT fp16
    vtrans_kernel<<<dim3(LL / 32, DD / 32, BB), 256>>>(gV);

    // 4) E = Q K^T / 16 (fp16 1-term) with fused softmax partials
    mm_e<<<dim3(LL / 128, LL / 128, BB), 256, SMEM2>>>(gE);

    // 5) softmax finalize
    softmax_combine<<<dim3(LL / 256, BB), 256>>>();

    // 6) C = A V (fp16 1-term; A from E on the fly; n-tiles split A writes)
    mm_av<<<dim3(DD / 128, LL / 128, BB), 256, SMEM2>>>(gE, Aout, Sp + (size_t)LL * DD);

    (void)in_sizes; (void)n_in; (void)out_size;
}